// round 14
// baseline (speedup 1.0000x reference)
#include <cuda_runtime.h>
#include <math.h>

#define BB 8
#define CC 256
#define LL 2048
#define HH 4
#define HD 64
#define NTOK (BB*LL)
#define BHN (BB*HH)

typedef unsigned long long u64;

__device__ float g_Q[BHN*HD*LL];   // d-major [bh][d][l]
__device__ float g_K[BHN*HD*LL];   // d-major [bh][d][l]
__device__ float g_V[BHN*LL*HD];   // l-major [bh][l][d]
__device__ float g_G[BHN*HD*HD];
__device__ float g_AT[NTOK*CC];

__device__ __forceinline__ u64 dup2(float x){ u64 r; asm("mov.b64 %0,{%1,%1};":"=l"(r):"f"(x)); return r; }
__device__ __forceinline__ void unpack2(u64 v, float& lo, float& hi){ asm("mov.b64 {%0,%1},%2;":"=f"(lo),"=f"(hi):"l"(v)); }
__device__ __forceinline__ u64 fma2(u64 a,u64 b,u64 c){ u64 d; asm("fma.rn.f32x2 %0,%1,%2,%3;":"=l"(d):"l"(a),"l"(b),"l"(c)); return d; }
__device__ __forceinline__ u64 mul2(u64 a,u64 b){ u64 d; asm("mul.rn.f32x2 %0,%1,%2;":"=l"(d):"l"(a),"l"(b)); return d; }
__device__ __forceinline__ u64 add2(u64 a,u64 b){ u64 d; asm("add.rn.f32x2 %0,%1,%2;":"=l"(d):"l"(a),"l"(b)); return d; }

__device__ __forceinline__ u64 exp_poly2(u64 t){
    u64 p = dup2(2.48015873e-5f);
    p = fma2(p, t, dup2(1.98412698e-4f));
    p = fma2(p, t, dup2(1.38888889e-3f));
    p = fma2(p, t, dup2(8.33333333e-3f));
    p = fma2(p, t, dup2(4.16666667e-2f));
    p = fma2(p, t, dup2(1.66666667e-1f));
    p = fma2(p, t, dup2(0.5f));
    p = fma2(p, t, dup2(1.0f));
    p = fma2(p, t, dup2(1.0f));
    return p;
}

__device__ __forceinline__ float gelu_exact(float x) {
    return 0.5f * x * (1.0f + erff(x * 0.70710678118654752f));
}

// ---- fused MLP (R13 exact) ---------------------------------------------------
__global__ void __launch_bounds__(256, 2) mlp_kernel(
    const float* __restrict__ x,
    const float* __restrict__ qw1, const float* __restrict__ qb1,
    const float* __restrict__ qw2, const float* __restrict__ qb2,
    const float* __restrict__ kw1, const float* __restrict__ kb1,
    const float* __restrict__ kw2, const float* __restrict__ kb2,
    const float* __restrict__ vw1, const float* __restrict__ vb1,
    const float* __restrict__ vw2, const float* __restrict__ vb2)
{
    extern __shared__ float sm[];
    float* xt = sm;                // [256][36]
    float* ht = sm + 256*36;
    float* ws = sm + 2*256*36;     // [32][256]

    const float *w1, *b1, *w2, *b2; float* out;
    if (blockIdx.y == 0)      { w1=qw1; b1=qb1; w2=qw2; b2=qb2; out=g_Q; }
    else if (blockIdx.y == 1) { w1=kw1; b1=kb1; w2=kw2; b2=kb2; out=g_K; }
    else                      { w1=vw1; b1=vb1; w2=vw2; b2=vb2; out=g_V; }

    const int b  = blockIdx.x >> 6;
    const int l0 = (blockIdx.x & 63) << 5;
    const int tid = threadIdx.x;

    const float* xb = x + (size_t)b*CC*LL + l0;
    #pragma unroll
    for (int r = 0; r < 32; r++) {
        int idx = tid + r*256;
        xt[(idx >> 5)*36 + (idx & 31)] = xb[(size_t)(idx >> 5)*LL + (idx & 31)];
    }

    const int tg = tid >> 5, fg = tid & 31;
    const int t0 = tg << 2;
    const int fa = fg << 2;

    u64 acc2[4][4];
    #pragma unroll
    for (int t = 0; t < 4; t++)
        #pragma unroll
        for (int p = 0; p < 4; p++) acc2[t][p] = 0ULL;

    for (int ks = 0; ks < 8; ks++) {
        __syncthreads();
        const float4* wsrc = (const float4*)(w1 + ks*32*256);
        float4* wdst = (float4*)ws;
        #pragma unroll
        for (int r = 0; r < 8; r++) wdst[tid + r*256] = wsrc[tid + r*256];
        __syncthreads();
        #pragma unroll 8
        for (int k = 0; k < 32; k++) {
            const float* wrow = ws + k*256 + fa;
            float4 av = *(const float4*)(xt + (ks*32 + k)*36 + t0);
            ulonglong2 wa = *(const ulonglong2*)(wrow);
            ulonglong2 wb = *(const ulonglong2*)(wrow + 128);
            u64 w[4] = {wa.x, wa.y, wb.x, wb.y};
            u64 d0 = dup2(av.x), d1 = dup2(av.y), d2 = dup2(av.z), d3 = dup2(av.w);
            #pragma unroll
            for (int p = 0; p < 4; p++) {
                acc2[0][p] = fma2(d0, w[p], acc2[0][p]);
                acc2[1][p] = fma2(d1, w[p], acc2[1][p]);
                acc2[2][p] = fma2(d2, w[p], acc2[2][p]);
                acc2[3][p] = fma2(d3, w[p], acc2[3][p]);
            }
        }
    }
    __syncthreads();
    {
        float4 ba = *(const float4*)(b1 + fa);
        float4 bb4 = *(const float4*)(b1 + 128 + fa);
        float bias[8] = {ba.x, ba.y, ba.z, ba.w, bb4.x, bb4.y, bb4.z, bb4.w};
        float g[4][8];
        #pragma unroll
        for (int t = 0; t < 4; t++) {
            unpack2(acc2[t][0], g[t][0], g[t][1]);
            unpack2(acc2[t][1], g[t][2], g[t][3]);
            unpack2(acc2[t][2], g[t][4], g[t][5]);
            unpack2(acc2[t][3], g[t][6], g[t][7]);
            #pragma unroll
            for (int p = 0; p < 4; p++) acc2[t][p] = 0ULL;
        }
        #pragma unroll
        for (int j = 0; j < 8; j++) {
            int F = (j < 4) ? (fa + j) : (128 + fa + j - 4);
            *(float4*)(ht + F*36 + t0) = make_float4(
                gelu_exact(g[0][j] + bias[j]), gelu_exact(g[1][j] + bias[j]),
                gelu_exact(g[2][j] + bias[j]), gelu_exact(g[3][j] + bias[j]));
        }
    }

    for (int ks = 0; ks < 8; ks++) {
        __syncthreads();
        const float4* wsrc = (const float4*)(w2 + ks*32*256);
        float4* wdst = (float4*)ws;
        #pragma unroll
        for (int r = 0; r < 8; r++) wdst[tid + r*256] = wsrc[tid + r*256];
        __syncthreads();
        #pragma unroll 8
        for (int k = 0; k < 32; k++) {
            const float* wrow = ws + k*256 + fa;
            float4 av = *(const float4*)(ht + (ks*32 + k)*36 + t0);
            ulonglong2 wa = *(const ulonglong2*)(wrow);
            ulonglong2 wb = *(const ulonglong2*)(wrow + 128);
            u64 w[4] = {wa.x, wa.y, wb.x, wb.y};
            u64 d0 = dup2(av.x), d1 = dup2(av.y), d2 = dup2(av.z), d3 = dup2(av.w);
            #pragma unroll
            for (int p = 0; p < 4; p++) {
                acc2[0][p] = fma2(d0, w[p], acc2[0][p]);
                acc2[1][p] = fma2(d1, w[p], acc2[1][p]);
                acc2[2][p] = fma2(d2, w[p], acc2[2][p]);
                acc2[3][p] = fma2(d3, w[p], acc2[3][p]);
            }
        }
    }

    {
        float4 ba = *(const float4*)(b2 + fa);
        float4 bb4 = *(const float4*)(b2 + 128 + fa);
        float bias[8] = {ba.x, ba.y, ba.z, ba.w, bb4.x, bb4.y, bb4.z, bb4.w};
        float o[4][8];
        #pragma unroll
        for (int t = 0; t < 4; t++) {
            unpack2(acc2[t][0], o[t][0], o[t][1]);
            unpack2(acc2[t][1], o[t][2], o[t][3]);
            unpack2(acc2[t][2], o[t][4], o[t][5]);
            unpack2(acc2[t][3], o[t][6], o[t][7]);
            #pragma unroll
            for (int j = 0; j < 8; j++) o[t][j] += bias[j];
        }

        if (blockIdx.y == 2) {
            #pragma unroll
            for (int j = 0; j < 8; j++) {
                int F = (j < 4) ? (fa + j) : (128 + fa + j - 4);
                int h = F >> 6, d = F & 63;
                float* op = out + (((size_t)(b*HH + h))*LL + l0 + t0)*HD + d;
                #pragma unroll
                for (int t = 0; t < 4; t++) op[t*HD] = o[t][j];
            }
        } else {
            __syncthreads();
            #pragma unroll
            for (int j = 0; j < 8; j++) {
                int F = (j < 4) ? (fa + j) : (128 + fa + j - 4);
                *(float4*)(xt + F*36 + t0) = make_float4(o[0][j], o[1][j], o[2][j], o[3][j]);
            }
            __syncthreads();
            #pragma unroll
            for (int r = 0; r < 8; r++) {
                int idx = tid + r*256;
                int f = idx >> 3, i4 = idx & 7;
                *(float4*)(out + ((size_t)b*256 + f)*LL + l0 + i4*4) =
                    *(const float4*)(xt + f*36 + i4*4);
            }
        }
    }
}

// ---- Gram: one CTA per bh, 8 slabs, direct write (no zero pass, no atomics) --
__global__ void __launch_bounds__(256) gram_kernel() {
    extern __shared__ float Ks[];   // [64][260]
    const int bh = blockIdx.x;
    const float* Kb = g_K + (size_t)bh*HD*LL;
    const int tid = threadIdx.x;
    const int d0 = (tid >> 4) << 2, e0 = (tid & 15) << 2;
    u64 acc2[4][4];
    #pragma unroll
    for (int i = 0; i < 4; i++)
        #pragma unroll
        for (int j = 0; j < 4; j++) acc2[i][j] = 0ULL;

    for (int sl = 0; sl < 8; sl++) {
        __syncthreads();
        #pragma unroll
        for (int r = 0; r < 16; r++) {
            int idx = tid + r*256;
            int d = idx >> 6, c4 = idx & 63;
            *(float4*)(Ks + d*260 + c4*4) = *(const float4*)(Kb + (size_t)d*LL + sl*256 + c4*4);
        }
        __syncthreads();
        #pragma unroll 4
        for (int k2 = 0; k2 < 128; k2++) {
            u64 a[4], bv[4];
            #pragma unroll
            for (int i = 0; i < 4; i++) a[i]  = *(const u64*)(Ks + (d0+i)*260 + 2*k2);
            #pragma unroll
            for (int j = 0; j < 4; j++) bv[j] = *(const u64*)(Ks + (e0+j)*260 + 2*k2);
            #pragma unroll
            for (int i = 0; i < 4; i++)
                #pragma unroll
                for (int j = 0; j < 4; j++)
                    acc2[i][j] = fma2(a[i], bv[j], acc2[i][j]);
        }
    }
    float* Gp = g_G + (size_t)bh*HD*HD;
    #pragma unroll
    for (int i = 0; i < 4; i++)
        #pragma unroll
        for (int j = 0; j < 4; j++) {
            float lo, hi; unpack2(acc2[i][j], lo, hi);
            Gp[(d0 + i)*HD + e0 + j] = lo + hi;
        }
}

// ---- attention (R7/R13 exact) -------------------------------------------------
#define ATT_SMEM_BYTES ((64*132 + 64*68 + 64*68 + 64*132 + 2*128)*4)
__global__ void __launch_bounds__(256, 2) attn_kernel() {
    extern __shared__ float sm[];
    float* Qt   = sm;
    float* Kt   = Qt + 64*132;
    float* Vs   = Kt + 64*68;
    float* Pt   = Vs + 64*68;
    float* invd = Pt + 64*132;
    float* psum = invd + 128;

    const int tid = threadIdx.x;
    const int bh  = blockIdx.y;
    const int q0g = blockIdx.x << 7;

    const float* Qb = g_Q + (size_t)bh*HD*LL;
    #pragma unroll
    for (int r = 0; r < 8; r++) {
        int idx = tid + r*256;
        int d = idx >> 5, c4 = idx & 31;
        *(float4*)(Qt + d*132 + c4*4) = *(const float4*)(Qb + (size_t)d*LL + q0g + c4*4);
    }
    {
        const float* Gb = g_G + (size_t)bh*HD*HD;
        #pragma unroll
        for (int r = 0; r < 4; r++) {
            int idx = tid + r*256;
            int d = idx >> 4, c4 = idx & 15;
            *(float4*)(Pt + d*68 + c4*4) = *(const float4*)(Gb + d*64 + c4*4);
        }
    }
    __syncthreads();

    {
        int q = tid & 127, half = tid >> 7;
        float part = 0.f;
        for (int d = half*32; d < half*32 + 32; d++) {
            float qd = Qt[d*132 + q];
            float t = 0.f;
            #pragma unroll 16
            for (int e = 0; e < 64; e++)
                t = fmaf(Pt[d*68 + e], Qt[e*132 + q], t);
            part = fmaf(qd, t, part);
        }
        if (half == 0) { invd[q] = part; }
        __syncthreads();
        if (half == 1) {
            float ssq = invd[q] + part;
            __syncthreads();
            invd[q] = 1.0f / (sqrtf(fmaxf(ssq, 0.f)) + 8.0e-12f);
            psum[q] = 0.f;
        } else __syncthreads();
    }
    __syncthreads();

    const int kz = tid >> 7;
    const int ty = (tid >> 3) & 15, tx = tid & 7;
    const int qr = ty << 3;
    const int kc = kz*32 + tx*4;
    const int qg = ((tid >> 4) & 15) << 3;
    const int dg = (tid & 15) << 2;

    u64 s2[4][4];
    u64 Oacc[4][4];
    #pragma unroll
    for (int p = 0; p < 4; p++)
        #pragma unroll
        for (int c = 0; c < 4; c++) Oacc[p][c] = 0ULL;
    u64 rs2[4] = {0ULL,0ULL,0ULL,0ULL};
    u64 invd2[4];
    #pragma unroll
    for (int p = 0; p < 4; p++) invd2[p] = ((const u64*)(invd + qr))[p];

    const float* Kb = g_K + (size_t)bh*HD*LL;
    const float* Vb = g_V + (size_t)bh*LL*HD;

    for (int kt = 0; kt < 32; kt++) {
        __syncthreads();
        const int k0 = kt << 6;
        #pragma unroll
        for (int r = 0; r < 4; r++) {
            int idx = tid + r*256;
            int d = idx >> 4, c4 = idx & 15;
            *(float4*)(Kt + d*68 + c4*4) = *(const float4*)(Kb + (size_t)d*LL + k0 + c4*4);
        }
        #pragma unroll
        for (int r = 0; r < 4; r++) {
            int idx = tid + r*256;
            int row = idx >> 4, c4 = idx & 15;
            *(float4*)(Vs + row*68 + c4*4) = *(const float4*)(Vb + (size_t)(k0 + row)*HD + c4*4);
        }
        __syncthreads();

        #pragma unroll
        for (int p = 0; p < 4; p++)
            #pragma unroll
            for (int j = 0; j < 4; j++) s2[p][j] = 0ULL;
        #pragma unroll 4
        for (int d = 0; d < 64; d++) {
            ulonglong2 qa = *(const ulonglong2*)(Qt + d*132 + qr);
            ulonglong2 qb2v = *(const ulonglong2*)(Qt + d*132 + qr + 4);
            u64 qp[4] = {qa.x, qa.y, qb2v.x, qb2v.y};
            float4 kv = *(const float4*)(Kt + d*68 + kc);
            u64 kd[4] = {dup2(kv.x), dup2(kv.y), dup2(kv.z), dup2(kv.w)};
            #pragma unroll
            for (int p = 0; p < 4; p++)
                #pragma unroll
                for (int j = 0; j < 4; j++)
                    s2[p][j] = fma2(qp[p], kd[j], s2[p][j]);
        }

        #pragma unroll
        for (int p = 0; p < 4; p++) {
            #pragma unroll
            for (int j = 0; j < 4; j++) {
                u64 e = exp_poly2(mul2(s2[p][j], invd2[p]));
                s2[p][j] = e;
                rs2[p] = add2(rs2[p], e);
            }
        }
        #pragma unroll
        for (int j = 0; j < 4; j++) {
            ulonglong2 lo, hi;
            lo.x = s2[0][j]; lo.y = s2[1][j];
            hi.x = s2[2][j]; hi.y = s2[3][j];
            *(ulonglong2*)(Pt + (kc + j)*132 + qr)     = lo;
            *(ulonglong2*)(Pt + (kc + j)*132 + qr + 4) = hi;
        }
        __syncthreads();

        #pragma unroll 2
        for (int k = 0; k < 64; k++) {
            ulonglong2 pa = *(const ulonglong2*)(Pt + k*132 + qg);
            ulonglong2 pb = *(const ulonglong2*)(Pt + k*132 + qg + 4);
            u64 pp[4] = {pa.x, pa.y, pb.x, pb.y};
            float4 vf = *(const float4*)(Vs + k*68 + dg);
            u64 vd[4] = {dup2(vf.x), dup2(vf.y), dup2(vf.z), dup2(vf.w)};
            #pragma unroll
            for (int p = 0; p < 4; p++)
                #pragma unroll
                for (int c = 0; c < 4; c++)
                    Oacc[p][c] = fma2(pp[p], vd[c], Oacc[p][c]);
        }
    }

    #pragma unroll
    for (int p = 0; p < 4; p++) {
        float lo, hi; unpack2(rs2[p], lo, hi);
        atomicAdd(&psum[qr + 2*p],     lo);
        atomicAdd(&psum[qr + 2*p + 1], hi);
    }
    __syncthreads();

    const int b = bh >> 2, h = bh & 3;
    #pragma unroll
    for (int p = 0; p < 4; p++) {
        float ilo = 1.0f / psum[qg + 2*p];
        float ihi = 1.0f / psum[qg + 2*p + 1];
        float olo[4], ohi[4];
        #pragma unroll
        for (int c = 0; c < 4; c++) unpack2(Oacc[p][c], olo[c], ohi[c]);
        size_t row0 = (size_t)(b*LL + q0g + qg + 2*p)*CC + h*HD + dg;
        size_t row1 = row0 + CC;
        *(float4*)(g_AT + row0) = make_float4(olo[0]*ilo, olo[1]*ilo, olo[2]*ilo, olo[3]*ilo);
        *(float4*)(g_AT + row1) = make_float4(ohi[0]*ihi, ohi[1]*ihi, ohi[2]*ihi, ohi[3]*ihi);
    }
}

// ---- O-proj + LN + ELU + residual (conflict-free f32x2 weights) --------------
__global__ void __launch_bounds__(256) out_kernel(
    const float* __restrict__ x_in, const float* __restrict__ ow,
    const float* __restrict__ ob, const float* __restrict__ lng,
    const float* __restrict__ lnb, float* __restrict__ out)
{
    extern __shared__ float sm[];
    float* at = sm;               // [256][36]
    float* ws = sm + 256*36;      // [32][256]

    const int tok0 = blockIdx.x << 5;
    const int b = tok0 >> 11, l0 = tok0 & (LL-1);
    const int tid = threadIdx.x;

    #pragma unroll
    for (int r = 0; r < 32; r++) {
        int idx = tid + r*256;
        int t = idx >> 8, k = idx & 255;
        at[k*36 + t] = g_AT[(size_t)(tok0 + t)*CC + k];
    }

    const int tg = tid >> 5, fg = tid & 31;
    const int t0 = tg << 2;
    const int fa = fg << 2;

    u64 acc2[4][4];                // [token][feature-pair]
    #pragma unroll
    for (int t = 0; t < 4; t++)
        #pragma unroll
        for (int p = 0; p < 4; p++) acc2[t][p] = 0ULL;

    for (int ks = 0; ks < 8; ks++) {
        __syncthreads();
        const float4* wsrc = (const float4*)(ow + ks*32*256);
        float4* wdst = (float4*)ws;
        #pragma unroll
        for (int r = 0; r < 8; r++) wdst[tid + r*256] = wsrc[tid + r*256];
        __syncthreads();
        #pragma unroll 8
        for (int k = 0; k < 32; k++) {
            const float* wrow = ws + k*256 + fa;
            float4 av = *(const float4*)(at + (ks*32 + k)*36 + t0);
            ulonglong2 wa = *(const ulonglong2*)(wrow);
            ulonglong2 wb = *(const ulonglong2*)(wrow + 128);
            u64 w[4] = {wa.x, wa.y, wb.x, wb.y};
            u64 d0 = dup2(av.x), d1 = dup2(av.y), d2 = dup2(av.z), d3 = dup2(av.w);
            #pragma unroll
            for (int p = 0; p < 4; p++) {
                acc2[0][p] = fma2(d0, w[p], acc2[0][p]);
                acc2[1][p] = fma2(d1, w[p], acc2[1][p]);
                acc2[2][p] = fma2(d2, w[p], acc2[2][p]);
                acc2[3][p] = fma2(d3, w[p], acc2[3][p]);
            }
        }
    }

    // unpack + bias; o[t][j]: j<4 -> feature fa+j, else 128+fa+j-4
    float o[4][8];
    float gv[8], bvv[8];
    {
        float4 ba = *(const float4*)(ob + fa);
        float4 bb4 = *(const float4*)(ob + 128 + fa);
        float bias[8] = {ba.x, ba.y, ba.z, ba.w, bb4.x, bb4.y, bb4.z, bb4.w};
        float4 ga = *(const float4*)(lng + fa);
        float4 gb4 = *(const float4*)(lng + 128 + fa);
        float4 be = *(const float4*)(lnb + fa);
        float4 be4 = *(const float4*)(lnb + 128 + fa);
        gv[0]=ga.x; gv[1]=ga.y; gv[2]=ga.z; gv[3]=ga.w;
        gv[4]=gb4.x; gv[5]=gb4.y; gv[6]=gb4.z; gv[7]=gb4.w;
        bvv[0]=be.x; bvv[1]=be.y; bvv[2]=be.z; bvv[3]=be.w;
        bvv[4]=be4.x; bvv[5]=be4.y; bvv[6]=be4.z; bvv[7]=be4.w;
        #pragma unroll
        for (int t = 0; t < 4; t++) {
            unpack2(acc2[t][0], o[t][0], o[t][1]);
            unpack2(acc2[t][1], o[t][2], o[t][3]);
            unpack2(acc2[t][2], o[t][4], o[t][5]);
            unpack2(acc2[t][3], o[t][6], o[t][7]);
            #pragma unroll
            for (int j = 0; j < 8; j++) o[t][j] += bias[j];
        }
    }
    __syncthreads();   // 'at' reuse below

    // LayerNorm: warp lanes cover all 256 features for this token group
    #pragma unroll
    for (int m = 0; m < 4; m++) {
        float s = 0.f, s2v = 0.f;
        #pragma unroll
        for (int j = 0; j < 8; j++) { s += o[m][j]; s2v = fmaf(o[m][j], o[m][j], s2v); }
        #pragma unroll
        for (int off = 16; off > 0; off >>= 1) {
            s   += __shfl_xor_sync(0xffffffffu, s,   off);
            s2v += __shfl_xor_sync(0xffffffffu, s2v, off);
        }
        float mu = s * (1.0f/256.0f);
        float var = fmaf(-mu, mu, s2v * (1.0f/256.0f));
        float rstd = rsqrtf(var + 1e-5f);
        #pragma unroll
        for (int j = 0; j < 8; j++) {
            int F = (j < 4) ? (fa + j) : (128 + fa + j - 4);
            at[F*36 + t0 + m] = fmaf((o[m][j] - mu) * rstd, gv[j], bvv[j]);
        }
    }
    __syncthreads();

    const float* xb = x_in + (size_t)b*CC*LL + l0;
    float* outb = out + (size_t)b*CC*LL + l0;
    #pragma unroll
    for (int r = 0; r < 32; r++) {
        int idx = tid + r*256;
        int t = idx & 31, f = idx >> 5;
        float y = at[f*36 + t];
        float e = (y > 0.f) ? y : expm1f(y);
        outb[(size_t)f*LL + t] = e + xb[(size_t)f*LL + t];
    }
}

extern "C" void kernel_launch(void* const* d_in, const int* in_sizes, int n_in,
                              void* d_out, int out_size) {
    const float* x    = (const float*)d_in[0];
    const float* qw1  = (const float*)d_in[1];
    const float* qb1  = (const float*)d_in[2];
    const float* qw2  = (const float*)d_in[3];
    const float* qb2  = (const float*)d_in[4];
    const float* kw1  = (const float*)d_in[5];
    const float* kb1  = (const float*)d_in[6];
    const float* kw2  = (const float*)d_in[7];
    const float* kb2  = (const float*)d_in[8];
    const float* vw1  = (const float*)d_in[9];
    const float* vb1  = (const float*)d_in[10];
    const float* vw2  = (const float*)d_in[11];
    const float* vb2  = (const float*)d_in[12];
    const float* ow   = (const float*)d_in[13];
    const float* ob   = (const float*)d_in[14];
    const float* lng  = (const float*)d_in[15];
    const float* lnb  = (const float*)d_in[16];
    float* out = (float*)d_out;

    const int mlp_smem  = (2*256*36 + 32*256)*4;
    const int out_smem  = (256*36 + 32*256)*4;
    const int gram_smem = 64*260*4;
    cudaFuncSetAttribute(mlp_kernel,  cudaFuncAttributeMaxDynamicSharedMemorySize, mlp_smem);
    cudaFuncSetAttribute(gram_kernel, cudaFuncAttributeMaxDynamicSharedMemorySize, gram_smem);
    cudaFuncSetAttribute(attn_kernel, cudaFuncAttributeMaxDynamicSharedMemorySize, ATT_SMEM_BYTES);
    cudaFuncSetAttribute(out_kernel,  cudaFuncAttributeMaxDynamicSharedMemorySize, out_smem);

    mlp_kernel<<<dim3(512, 3), 256, mlp_smem>>>(x, qw1, qb1, qw2, qb2,
                                                kw1, kb1, kw2, kb2,
                                                vw1, vb1, vw2, vb2);
    gram_kernel<<<32, 256, gram_smem>>>();
    attn_kernel<<<dim3(16, 32), 256, ATT_SMEM_BYTES>>>();
    out_kernel<<<512, 256, out_smem>>>(x, ow, ob, lng, lnb, out);
}

// round 15
// speedup vs baseline: 1.0902x; 1.0902x over previous
#include <cuda_runtime.h>
#include <math.h>

#define BB 8
#define CC 256
#define LL 2048
#define HH 4
#define HD 64
#define NTOK (BB*LL)
#define BHN (BB*HH)

typedef unsigned long long u64;

__device__ float g_Q[BHN*HD*LL];   // d-major [bh][d][l]
__device__ float g_K[BHN*HD*LL];   // d-major [bh][d][l]
__device__ float g_V[BHN*LL*HD];   // l-major [bh][l][d]
__device__ float g_G[BHN*HD*HD];
__device__ float g_AT[NTOK*CC];

__device__ __forceinline__ u64 dup2(float x){ u64 r; asm("mov.b64 %0,{%1,%1};":"=l"(r):"f"(x)); return r; }
__device__ __forceinline__ void unpack2(u64 v, float& lo, float& hi){ asm("mov.b64 {%0,%1},%2;":"=f"(lo),"=f"(hi):"l"(v)); }
__device__ __forceinline__ u64 fma2(u64 a,u64 b,u64 c){ u64 d; asm("fma.rn.f32x2 %0,%1,%2,%3;":"=l"(d):"l"(a),"l"(b),"l"(c)); return d; }
__device__ __forceinline__ u64 mul2(u64 a,u64 b){ u64 d; asm("mul.rn.f32x2 %0,%1,%2;":"=l"(d):"l"(a),"l"(b)); return d; }
__device__ __forceinline__ u64 add2(u64 a,u64 b){ u64 d; asm("add.rn.f32x2 %0,%1,%2;":"=l"(d):"l"(a),"l"(b)); return d; }

__device__ __forceinline__ u64 exp_poly2(u64 t){
    u64 p = dup2(2.48015873e-5f);
    p = fma2(p, t, dup2(1.98412698e-4f));
    p = fma2(p, t, dup2(1.38888889e-3f));
    p = fma2(p, t, dup2(8.33333333e-3f));
    p = fma2(p, t, dup2(4.16666667e-2f));
    p = fma2(p, t, dup2(1.66666667e-1f));
    p = fma2(p, t, dup2(0.5f));
    p = fma2(p, t, dup2(1.0f));
    p = fma2(p, t, dup2(1.0f));
    return p;
}

__device__ __forceinline__ float gelu_exact(float x) {
    return 0.5f * x * (1.0f + erff(x * 0.70710678118654752f));
}

__global__ void zero_G_kernel() {
    int n = BHN*HD*HD;
    for (int i = blockIdx.x*blockDim.x + threadIdx.x; i < n; i += gridDim.x*blockDim.x)
        g_G[i] = 0.f;
}

// ---- fused MLP (R13 exact) ---------------------------------------------------
__global__ void __launch_bounds__(256, 2) mlp_kernel(
    const float* __restrict__ x,
    const float* __restrict__ qw1, const float* __restrict__ qb1,
    const float* __restrict__ qw2, const float* __restrict__ qb2,
    const float* __restrict__ kw1, const float* __restrict__ kb1,
    const float* __restrict__ kw2, const float* __restrict__ kb2,
    const float* __restrict__ vw1, const float* __restrict__ vb1,
    const float* __restrict__ vw2, const float* __restrict__ vb2)
{
    extern __shared__ float sm[];
    float* xt = sm;                // [256][36]
    float* ht = sm + 256*36;
    float* ws = sm + 2*256*36;     // [32][256]

    const float *w1, *b1, *w2, *b2; float* out;
    if (blockIdx.y == 0)      { w1=qw1; b1=qb1; w2=qw2; b2=qb2; out=g_Q; }
    else if (blockIdx.y == 1) { w1=kw1; b1=kb1; w2=kw2; b2=kb2; out=g_K; }
    else                      { w1=vw1; b1=vb1; w2=vw2; b2=vb2; out=g_V; }

    const int b  = blockIdx.x >> 6;
    const int l0 = (blockIdx.x & 63) << 5;
    const int tid = threadIdx.x;

    const float* xb = x + (size_t)b*CC*LL + l0;
    #pragma unroll
    for (int r = 0; r < 32; r++) {
        int idx = tid + r*256;
        xt[(idx >> 5)*36 + (idx & 31)] = xb[(size_t)(idx >> 5)*LL + (idx & 31)];
    }

    const int tg = tid >> 5, fg = tid & 31;
    const int t0 = tg << 2;
    const int fa = fg << 2;

    u64 acc2[4][4];
    #pragma unroll
    for (int t = 0; t < 4; t++)
        #pragma unroll
        for (int p = 0; p < 4; p++) acc2[t][p] = 0ULL;

    for (int ks = 0; ks < 8; ks++) {
        __syncthreads();
        const float4* wsrc = (const float4*)(w1 + ks*32*256);
        float4* wdst = (float4*)ws;
        #pragma unroll
        for (int r = 0; r < 8; r++) wdst[tid + r*256] = wsrc[tid + r*256];
        __syncthreads();
        #pragma unroll 8
        for (int k = 0; k < 32; k++) {
            const float* wrow = ws + k*256 + fa;
            float4 av = *(const float4*)(xt + (ks*32 + k)*36 + t0);
            ulonglong2 wa = *(const ulonglong2*)(wrow);
            ulonglong2 wb = *(const ulonglong2*)(wrow + 128);
            u64 w[4] = {wa.x, wa.y, wb.x, wb.y};
            u64 d0 = dup2(av.x), d1 = dup2(av.y), d2 = dup2(av.z), d3 = dup2(av.w);
            #pragma unroll
            for (int p = 0; p < 4; p++) {
                acc2[0][p] = fma2(d0, w[p], acc2[0][p]);
                acc2[1][p] = fma2(d1, w[p], acc2[1][p]);
                acc2[2][p] = fma2(d2, w[p], acc2[2][p]);
                acc2[3][p] = fma2(d3, w[p], acc2[3][p]);
            }
        }
    }
    __syncthreads();
    {
        float4 ba = *(const float4*)(b1 + fa);
        float4 bb4 = *(const float4*)(b1 + 128 + fa);
        float bias[8] = {ba.x, ba.y, ba.z, ba.w, bb4.x, bb4.y, bb4.z, bb4.w};
        float g[4][8];
        #pragma unroll
        for (int t = 0; t < 4; t++) {
            unpack2(acc2[t][0], g[t][0], g[t][1]);
            unpack2(acc2[t][1], g[t][2], g[t][3]);
            unpack2(acc2[t][2], g[t][4], g[t][5]);
            unpack2(acc2[t][3], g[t][6], g[t][7]);
            #pragma unroll
            for (int p = 0; p < 4; p++) acc2[t][p] = 0ULL;
        }
        #pragma unroll
        for (int j = 0; j < 8; j++) {
            int F = (j < 4) ? (fa + j) : (128 + fa + j - 4);
            *(float4*)(ht + F*36 + t0) = make_float4(
                gelu_exact(g[0][j] + bias[j]), gelu_exact(g[1][j] + bias[j]),
                gelu_exact(g[2][j] + bias[j]), gelu_exact(g[3][j] + bias[j]));
        }
    }

    for (int ks = 0; ks < 8; ks++) {
        __syncthreads();
        const float4* wsrc = (const float4*)(w2 + ks*32*256);
        float4* wdst = (float4*)ws;
        #pragma unroll
        for (int r = 0; r < 8; r++) wdst[tid + r*256] = wsrc[tid + r*256];
        __syncthreads();
        #pragma unroll 8
        for (int k = 0; k < 32; k++) {
            const float* wrow = ws + k*256 + fa;
            float4 av = *(const float4*)(ht + (ks*32 + k)*36 + t0);
            ulonglong2 wa = *(const ulonglong2*)(wrow);
            ulonglong2 wb = *(const ulonglong2*)(wrow + 128);
            u64 w[4] = {wa.x, wa.y, wb.x, wb.y};
            u64 d0 = dup2(av.x), d1 = dup2(av.y), d2 = dup2(av.z), d3 = dup2(av.w);
            #pragma unroll
            for (int p = 0; p < 4; p++) {
                acc2[0][p] = fma2(d0, w[p], acc2[0][p]);
                acc2[1][p] = fma2(d1, w[p], acc2[1][p]);
                acc2[2][p] = fma2(d2, w[p], acc2[2][p]);
                acc2[3][p] = fma2(d3, w[p], acc2[3][p]);
            }
        }
    }

    {
        float4 ba = *(const float4*)(b2 + fa);
        float4 bb4 = *(const float4*)(b2 + 128 + fa);
        float bias[8] = {ba.x, ba.y, ba.z, ba.w, bb4.x, bb4.y, bb4.z, bb4.w};
        float o[4][8];
        #pragma unroll
        for (int t = 0; t < 4; t++) {
            unpack2(acc2[t][0], o[t][0], o[t][1]);
            unpack2(acc2[t][1], o[t][2], o[t][3]);
            unpack2(acc2[t][2], o[t][4], o[t][5]);
            unpack2(acc2[t][3], o[t][6], o[t][7]);
            #pragma unroll
            for (int j = 0; j < 8; j++) o[t][j] += bias[j];
        }

        if (blockIdx.y == 2) {
            #pragma unroll
            for (int j = 0; j < 8; j++) {
                int F = (j < 4) ? (fa + j) : (128 + fa + j - 4);
                int h = F >> 6, d = F & 63;
                float* op = out + (((size_t)(b*HH + h))*LL + l0 + t0)*HD + d;
                #pragma unroll
                for (int t = 0; t < 4; t++) op[t*HD] = o[t][j];
            }
        } else {
            __syncthreads();
            #pragma unroll
            for (int j = 0; j < 8; j++) {
                int F = (j < 4) ? (fa + j) : (128 + fa + j - 4);
                *(float4*)(xt + F*36 + t0) = make_float4(o[0][j], o[1][j], o[2][j], o[3][j]);
            }
            __syncthreads();
            #pragma unroll
            for (int r = 0; r < 8; r++) {
                int idx = tid + r*256;
                int f = idx >> 3, i4 = idx & 7;
                *(float4*)(out + ((size_t)b*256 + f)*LL + l0 + i4*4) =
                    *(const float4*)(xt + f*36 + i4*4);
            }
        }
    }
}

// ---- Gram (R13 exact: grid(32,8), atomics) ------------------------------------
__global__ void __launch_bounds__(256) gram_kernel() {
    extern __shared__ float Ks[];   // [64][260]
    const int bh = blockIdx.x, sl = blockIdx.y;
    const float* Kb = g_K + (size_t)bh*HD*LL;
    const int tid = threadIdx.x;
    const int d0 = (tid >> 4) << 2, e0 = (tid & 15) << 2;
    u64 acc2[4][4];
    #pragma unroll
    for (int i = 0; i < 4; i++)
        #pragma unroll
        for (int j = 0; j < 4; j++) acc2[i][j] = 0ULL;

    #pragma unroll
    for (int r = 0; r < 16; r++) {
        int idx = tid + r*256;
        int d = idx >> 6, c4 = idx & 63;
        *(float4*)(Ks + d*260 + c4*4) = *(const float4*)(Kb + (size_t)d*LL + sl*256 + c4*4);
    }
    __syncthreads();
    #pragma unroll 4
    for (int k2 = 0; k2 < 128; k2++) {
        u64 a[4], bv[4];
        #pragma unroll
        for (int i = 0; i < 4; i++) a[i]  = *(const u64*)(Ks + (d0+i)*260 + 2*k2);
        #pragma unroll
        for (int j = 0; j < 4; j++) bv[j] = *(const u64*)(Ks + (e0+j)*260 + 2*k2);
        #pragma unroll
        for (int i = 0; i < 4; i++)
            #pragma unroll
            for (int j = 0; j < 4; j++)
                acc2[i][j] = fma2(a[i], bv[j], acc2[i][j]);
    }
    float* Gp = g_G + (size_t)bh*HD*HD;
    #pragma unroll
    for (int i = 0; i < 4; i++)
        #pragma unroll
        for (int j = 0; j < 4; j++) {
            float lo, hi; unpack2(acc2[i][j], lo, hi);
            atomicAdd(Gp + (d0 + i)*HD + e0 + j, lo + hi);
        }
}

// ---- attention (R7/R13 exact) -------------------------------------------------
#define ATT_SMEM_BYTES ((64*132 + 64*68 + 64*68 + 64*132 + 2*128)*4)
__global__ void __launch_bounds__(256, 2) attn_kernel() {
    extern __shared__ float sm[];
    float* Qt   = sm;
    float* Kt   = Qt + 64*132;
    float* Vs   = Kt + 64*68;
    float* Pt   = Vs + 64*68;
    float* invd = Pt + 64*132;
    float* psum = invd + 128;

    const int tid = threadIdx.x;
    const int bh  = blockIdx.y;
    const int q0g = blockIdx.x << 7;

    const float* Qb = g_Q + (size_t)bh*HD*LL;
    #pragma unroll
    for (int r = 0; r < 8; r++) {
        int idx = tid + r*256;
        int d = idx >> 5, c4 = idx & 31;
        *(float4*)(Qt + d*132 + c4*4) = *(const float4*)(Qb + (size_t)d*LL + q0g + c4*4);
    }
    {
        const float* Gb = g_G + (size_t)bh*HD*HD;
        #pragma unroll
        for (int r = 0; r < 4; r++) {
            int idx = tid + r*256;
            int d = idx >> 4, c4 = idx & 15;
            *(float4*)(Pt + d*68 + c4*4) = *(const float4*)(Gb + d*64 + c4*4);
        }
    }
    __syncthreads();

    {
        int q = tid & 127, half = tid >> 7;
        float part = 0.f;
        for (int d = half*32; d < half*32 + 32; d++) {
            float qd = Qt[d*132 + q];
            float t = 0.f;
            #pragma unroll 16
            for (int e = 0; e < 64; e++)
                t = fmaf(Pt[d*68 + e], Qt[e*132 + q], t);
            part = fmaf(qd, t, part);
        }
        if (half == 0) { invd[q] = part; }
        __syncthreads();
        if (half == 1) {
            float ssq = invd[q] + part;
            __syncthreads();
            invd[q] = 1.0f / (sqrtf(fmaxf(ssq, 0.f)) + 8.0e-12f);
            psum[q] = 0.f;
        } else __syncthreads();
    }
    __syncthreads();

    const int kz = tid >> 7;
    const int ty = (tid >> 3) & 15, tx = tid & 7;
    const int qr = ty << 3;
    const int kc = kz*32 + tx*4;
    const int qg = ((tid >> 4) & 15) << 3;
    const int dg = (tid & 15) << 2;

    u64 s2[4][4];
    u64 Oacc[4][4];
    #pragma unroll
    for (int p = 0; p < 4; p++)
        #pragma unroll
        for (int c = 0; c < 4; c++) Oacc[p][c] = 0ULL;
    u64 rs2[4] = {0ULL,0ULL,0ULL,0ULL};
    u64 invd2[4];
    #pragma unroll
    for (int p = 0; p < 4; p++) invd2[p] = ((const u64*)(invd + qr))[p];

    const float* Kb = g_K + (size_t)bh*HD*LL;
    const float* Vb = g_V + (size_t)bh*LL*HD;

    for (int kt = 0; kt < 32; kt++) {
        __syncthreads();
        const int k0 = kt << 6;
        #pragma unroll
        for (int r = 0; r < 4; r++) {
            int idx = tid + r*256;
            int d = idx >> 4, c4 = idx & 15;
            *(float4*)(Kt + d*68 + c4*4) = *(const float4*)(Kb + (size_t)d*LL + k0 + c4*4);
        }
        #pragma unroll
        for (int r = 0; r < 4; r++) {
            int idx = tid + r*256;
            int row = idx >> 4, c4 = idx & 15;
            *(float4*)(Vs + row*68 + c4*4) = *(const float4*)(Vb + (size_t)(k0 + row)*HD + c4*4);
        }
        __syncthreads();

        #pragma unroll
        for (int p = 0; p < 4; p++)
            #pragma unroll
            for (int j = 0; j < 4; j++) s2[p][j] = 0ULL;
        #pragma unroll 4
        for (int d = 0; d < 64; d++) {
            ulonglong2 qa = *(const ulonglong2*)(Qt + d*132 + qr);
            ulonglong2 qb2v = *(const ulonglong2*)(Qt + d*132 + qr + 4);
            u64 qp[4] = {qa.x, qa.y, qb2v.x, qb2v.y};
            float4 kv = *(const float4*)(Kt + d*68 + kc);
            u64 kd[4] = {dup2(kv.x), dup2(kv.y), dup2(kv.z), dup2(kv.w)};
            #pragma unroll
            for (int p = 0; p < 4; p++)
                #pragma unroll
                for (int j = 0; j < 4; j++)
                    s2[p][j] = fma2(qp[p], kd[j], s2[p][j]);
        }

        #pragma unroll
        for (int p = 0; p < 4; p++) {
            #pragma unroll
            for (int j = 0; j < 4; j++) {
                u64 e = exp_poly2(mul2(s2[p][j], invd2[p]));
                s2[p][j] = e;
                rs2[p] = add2(rs2[p], e);
            }
        }
        #pragma unroll
        for (int j = 0; j < 4; j++) {
            ulonglong2 lo, hi;
            lo.x = s2[0][j]; lo.y = s2[1][j];
            hi.x = s2[2][j]; hi.y = s2[3][j];
            *(ulonglong2*)(Pt + (kc + j)*132 + qr)     = lo;
            *(ulonglong2*)(Pt + (kc + j)*132 + qr + 4) = hi;
        }
        __syncthreads();

        #pragma unroll 2
        for (int k = 0; k < 64; k++) {
            ulonglong2 pa = *(const ulonglong2*)(Pt + k*132 + qg);
            ulonglong2 pb = *(const ulonglong2*)(Pt + k*132 + qg + 4);
            u64 pp[4] = {pa.x, pa.y, pb.x, pb.y};
            float4 vf = *(const float4*)(Vs + k*68 + dg);
            u64 vd[4] = {dup2(vf.x), dup2(vf.y), dup2(vf.z), dup2(vf.w)};
            #pragma unroll
            for (int p = 0; p < 4; p++)
                #pragma unroll
                for (int c = 0; c < 4; c++)
                    Oacc[p][c] = fma2(pp[p], vd[c], Oacc[p][c]);
        }
    }

    #pragma unroll
    for (int p = 0; p < 4; p++) {
        float lo, hi; unpack2(rs2[p], lo, hi);
        atomicAdd(&psum[qr + 2*p],     lo);
        atomicAdd(&psum[qr + 2*p + 1], hi);
    }
    __syncthreads();

    const int b = bh >> 2, h = bh & 3;
    #pragma unroll
    for (int p = 0; p < 4; p++) {
        float ilo = 1.0f / psum[qg + 2*p];
        float ihi = 1.0f / psum[qg + 2*p + 1];
        float olo[4], ohi[4];
        #pragma unroll
        for (int c = 0; c < 4; c++) unpack2(Oacc[p][c], olo[c], ohi[c]);
        size_t row0 = (size_t)(b*LL + q0g + qg + 2*p)*CC + h*HD + dg;
        size_t row1 = row0 + CC;
        *(float4*)(g_AT + row0) = make_float4(olo[0]*ilo, olo[1]*ilo, olo[2]*ilo, olo[3]*ilo);
        *(float4*)(g_AT + row1) = make_float4(ohi[0]*ihi, ohi[1]*ihi, ohi[2]*ihi, ohi[3]*ihi);
    }
}

// ---- O-proj + LN + ELU + residual (R14's conflict-free f32x2 weights) ---------
__global__ void __launch_bounds__(256) out_kernel(
    const float* __restrict__ x_in, const float* __restrict__ ow,
    const float* __restrict__ ob, const float* __restrict__ lng,
    const float* __restrict__ lnb, float* __restrict__ out)
{
    extern __shared__ float sm[];
    float* at = sm;               // [256][36]
    float* ws = sm + 256*36;      // [32][256]

    const int tok0 = blockIdx.x << 5;
    const int b = tok0 >> 11, l0 = tok0 & (LL-1);
    const int tid = threadIdx.x;

    #pragma unroll
    for (int r = 0; r < 32; r++) {
        int idx = tid + r*256;
        int t = idx >> 8, k = idx & 255;
        at[k*36 + t] = g_AT[(size_t)(tok0 + t)*CC + k];
    }

    const int tg = tid >> 5, fg = tid & 31;
    const int t0 = tg << 2;
    const int fa = fg << 2;

    u64 acc2[4][4];
    #pragma unroll
    for (int t = 0; t < 4; t++)
        #pragma unroll
        for (int p = 0; p < 4; p++) acc2[t][p] = 0ULL;

    for (int ks = 0; ks < 8; ks++) {
        __syncthreads();
        const float4* wsrc = (const float4*)(ow + ks*32*256);
        float4* wdst = (float4*)ws;
        #pragma unroll
        for (int r = 0; r < 8; r++) wdst[tid + r*256] = wsrc[tid + r*256];
        __syncthreads();
        #pragma unroll 8
        for (int k = 0; k < 32; k++) {
            const float* wrow = ws + k*256 + fa;
            float4 av = *(const float4*)(at + (ks*32 + k)*36 + t0);
            ulonglong2 wa = *(const ulonglong2*)(wrow);
            ulonglong2 wb = *(const ulonglong2*)(wrow + 128);
            u64 w[4] = {wa.x, wa.y, wb.x, wb.y};
            u64 d0 = dup2(av.x), d1 = dup2(av.y), d2 = dup2(av.z), d3 = dup2(av.w);
            #pragma unroll
            for (int p = 0; p < 4; p++) {
                acc2[0][p] = fma2(d0, w[p], acc2[0][p]);
                acc2[1][p] = fma2(d1, w[p], acc2[1][p]);
                acc2[2][p] = fma2(d2, w[p], acc2[2][p]);
                acc2[3][p] = fma2(d3, w[p], acc2[3][p]);
            }
        }
    }

    float o[4][8];
    float gv[8], bvv[8];
    {
        float4 ba = *(const float4*)(ob + fa);
        float4 bb4 = *(const float4*)(ob + 128 + fa);
        float bias[8] = {ba.x, ba.y, ba.z, ba.w, bb4.x, bb4.y, bb4.z, bb4.w};
        float4 ga = *(const float4*)(lng + fa);
        float4 gb4 = *(const float4*)(lng + 128 + fa);
        float4 be = *(const float4*)(lnb + fa);
        float4 be4 = *(const float4*)(lnb + 128 + fa);
        gv[0]=ga.x; gv[1]=ga.y; gv[2]=ga.z; gv[3]=ga.w;
        gv[4]=gb4.x; gv[5]=gb4.y; gv[6]=gb4.z; gv[7]=gb4.w;
        bvv[0]=be.x; bvv[1]=be.y; bvv[2]=be.z; bvv[3]=be.w;
        bvv[4]=be4.x; bvv[5]=be4.y; bvv[6]=be4.z; bvv[7]=be4.w;
        #pragma unroll
        for (int t = 0; t < 4; t++) {
            unpack2(acc2[t][0], o[t][0], o[t][1]);
            unpack2(acc2[t][1], o[t][2], o[t][3]);
            unpack2(acc2[t][2], o[t][4], o[t][5]);
            unpack2(acc2[t][3], o[t][6], o[t][7]);
            #pragma unroll
            for (int j = 0; j < 8; j++) o[t][j] += bias[j];
        }
    }
    __syncthreads();

    #pragma unroll
    for (int m = 0; m < 4; m++) {
        float s = 0.f, s2v = 0.f;
        #pragma unroll
        for (int j = 0; j < 8; j++) { s += o[m][j]; s2v = fmaf(o[m][j], o[m][j], s2v); }
        #pragma unroll
        for (int off = 16; off > 0; off >>= 1) {
            s   += __shfl_xor_sync(0xffffffffu, s,   off);
            s2v += __shfl_xor_sync(0xffffffffu, s2v, off);
        }
        float mu = s * (1.0f/256.0f);
        float var = fmaf(-mu, mu, s2v * (1.0f/256.0f));
        float rstd = rsqrtf(var + 1e-5f);
        #pragma unroll
        for (int j = 0; j < 8; j++) {
            int F = (j < 4) ? (fa + j) : (128 + fa + j - 4);
            at[F*36 + t0 + m] = fmaf((o[m][j] - mu) * rstd, gv[j], bvv[j]);
        }
    }
    __syncthreads();

    const float* xb = x_in + (size_t)b*CC*LL + l0;
    float* outb = out + (size_t)b*CC*LL + l0;
    #pragma unroll
    for (int r = 0; r < 32; r++) {
        int idx = tid + r*256;
        int t = idx & 31, f = idx >> 5;
        float y = at[f*36 + t];
        float e = (y > 0.f) ? y : expm1f(y);
        outb[(size_t)f*LL + t] = e + xb[(size_t)f*LL + t];
    }
}

extern "C" void kernel_launch(void* const* d_in, const int* in_sizes, int n_in,
                              void* d_out, int out_size) {
    const float* x    = (const float*)d_in[0];
    const float* qw1  = (const float*)d_in[1];
    const float* qb1  = (const float*)d_in[2];
    const float* qw2  = (const float*)d_in[3];
    const float* qb2  = (const float*)d_in[4];
    const float* kw1  = (const float*)d_in[5];
    const float* kb1  = (const float*)d_in[6];
    const float* kw2  = (const float*)d_in[7];
    const float* kb2  = (const float*)d_in[8];
    const float* vw1  = (const float*)d_in[9];
    const float* vb1  = (const float*)d_in[10];
    const float* vw2  = (const float*)d_in[11];
    const float* vb2  = (const float*)d_in[12];
    const float* ow   = (const float*)d_in[13];
    const float* ob   = (const float*)d_in[14];
    const float* lng  = (const float*)d_in[15];
    const float* lnb  = (const float*)d_in[16];
    float* out = (float*)d_out;

    const int mlp_smem  = (2*256*36 + 32*256)*4;
    const int out_smem  = (256*36 + 32*256)*4;
    const int gram_smem = 64*260*4;
    cudaFuncSetAttribute(mlp_kernel,  cudaFuncAttributeMaxDynamicSharedMemorySize, mlp_smem);
    cudaFuncSetAttribute(gram_kernel, cudaFuncAttributeMaxDynamicSharedMemorySize, gram_smem);
    cudaFuncSetAttribute(attn_kernel, cudaFuncAttributeMaxDynamicSharedMemorySize, ATT_SMEM_BYTES);
    cudaFuncSetAttribute(out_kernel,  cudaFuncAttributeMaxDynamicSharedMemorySize, out_smem);

    zero_G_kernel<<<128, 256>>>();
    mlp_kernel<<<dim3(512, 3), 256, mlp_smem>>>(x, qw1, qb1, qw2, qb2,
                                                kw1, kb1, kw2, kb2,
                                                vw1, vb1, vw2, vb2);
    gram_kernel<<<dim3(32, 8), 256, gram_smem>>>();
    attn_kernel<<<dim3(16, 32), 256, ATT_SMEM_BYTES>>>();
    out_kernel<<<512, 256, out_smem>>>(x, ow, ob, lng, lnb, out);
}

// round 16
// speedup vs baseline: 1.0902x; 1.0000x over previous
#include <cuda_runtime.h>
#include <math.h>

#define BB 8
#define CC 256
#define LL 2048
#define HH 4
#define HD 64
#define NTOK (BB*LL)
#define BHN (BB*HH)

typedef unsigned long long u64;

__device__ float g_Q[BHN*HD*LL];   // d-major [bh][d][l]
__device__ float g_K[BHN*HD*LL];   // d-major [bh][d][l]
__device__ float g_V[BHN*LL*HD];   // l-major [bh][l][d]
__device__ float g_G[BHN*HD*HD];
__device__ float g_AT[NTOK*CC];

__device__ __forceinline__ u64 dup2(float x){ u64 r; asm("mov.b64 %0,{%1,%1};":"=l"(r):"f"(x)); return r; }
__device__ __forceinline__ void unpack2(u64 v, float& lo, float& hi){ asm("mov.b64 {%0,%1},%2;":"=f"(lo),"=f"(hi):"l"(v)); }
__device__ __forceinline__ u64 fma2(u64 a,u64 b,u64 c){ u64 d; asm("fma.rn.f32x2 %0,%1,%2,%3;":"=l"(d):"l"(a),"l"(b),"l"(c)); return d; }
__device__ __forceinline__ u64 mul2(u64 a,u64 b){ u64 d; asm("mul.rn.f32x2 %0,%1,%2;":"=l"(d):"l"(a),"l"(b)); return d; }
__device__ __forceinline__ u64 add2(u64 a,u64 b){ u64 d; asm("add.rn.f32x2 %0,%1,%2;":"=l"(d):"l"(a),"l"(b)); return d; }

__device__ __forceinline__ u64 exp_poly2(u64 t){
    u64 p = dup2(2.48015873e-5f);
    p = fma2(p, t, dup2(1.98412698e-4f));
    p = fma2(p, t, dup2(1.38888889e-3f));
    p = fma2(p, t, dup2(8.33333333e-3f));
    p = fma2(p, t, dup2(4.16666667e-2f));
    p = fma2(p, t, dup2(1.66666667e-1f));
    p = fma2(p, t, dup2(0.5f));
    p = fma2(p, t, dup2(1.0f));
    p = fma2(p, t, dup2(1.0f));
    return p;
}

__device__ __forceinline__ float gelu_exact(float x) {
    return 0.5f * x * (1.0f + erff(x * 0.70710678118654752f));
}

__global__ void zero_G_kernel() {
    int n = BHN*HD*HD;
    for (int i = blockIdx.x*blockDim.x + threadIdx.x; i < n; i += gridDim.x*blockDim.x)
        g_G[i] = 0.f;
}

// ---- fused MLP (R13 exact) ---------------------------------------------------
__global__ void __launch_bounds__(256, 2) mlp_kernel(
    const float* __restrict__ x,
    const float* __restrict__ qw1, const float* __restrict__ qb1,
    const float* __restrict__ qw2, const float* __restrict__ qb2,
    const float* __restrict__ kw1, const float* __restrict__ kb1,
    const float* __restrict__ kw2, const float* __restrict__ kb2,
    const float* __restrict__ vw1, const float* __restrict__ vb1,
    const float* __restrict__ vw2, const float* __restrict__ vb2)
{
    extern __shared__ float sm[];
    float* xt = sm;                // [256][36]
    float* ht = sm + 256*36;
    float* ws = sm + 2*256*36;     // [32][256]

    const float *w1, *b1, *w2, *b2; float* out;
    if (blockIdx.y == 0)      { w1=qw1; b1=qb1; w2=qw2; b2=qb2; out=g_Q; }
    else if (blockIdx.y == 1) { w1=kw1; b1=kb1; w2=kw2; b2=kb2; out=g_K; }
    else                      { w1=vw1; b1=vb1; w2=vw2; b2=vb2; out=g_V; }

    const int b  = blockIdx.x >> 6;
    const int l0 = (blockIdx.x & 63) << 5;
    const int tid = threadIdx.x;

    const float* xb = x + (size_t)b*CC*LL + l0;
    #pragma unroll
    for (int r = 0; r < 32; r++) {
        int idx = tid + r*256;
        xt[(idx >> 5)*36 + (idx & 31)] = xb[(size_t)(idx >> 5)*LL + (idx & 31)];
    }

    const int tg = tid >> 5, fg = tid & 31;
    const int t0 = tg << 2;
    const int fa = fg << 2;

    u64 acc2[4][4];
    #pragma unroll
    for (int t = 0; t < 4; t++)
        #pragma unroll
        for (int p = 0; p < 4; p++) acc2[t][p] = 0ULL;

    for (int ks = 0; ks < 8; ks++) {
        __syncthreads();
        const float4* wsrc = (const float4*)(w1 + ks*32*256);
        float4* wdst = (float4*)ws;
        #pragma unroll
        for (int r = 0; r < 8; r++) wdst[tid + r*256] = wsrc[tid + r*256];
        __syncthreads();
        #pragma unroll 8
        for (int k = 0; k < 32; k++) {
            const float* wrow = ws + k*256 + fa;
            float4 av = *(const float4*)(xt + (ks*32 + k)*36 + t0);
            ulonglong2 wa = *(const ulonglong2*)(wrow);
            ulonglong2 wb = *(const ulonglong2*)(wrow + 128);
            u64 w[4] = {wa.x, wa.y, wb.x, wb.y};
            u64 d0 = dup2(av.x), d1 = dup2(av.y), d2 = dup2(av.z), d3 = dup2(av.w);
            #pragma unroll
            for (int p = 0; p < 4; p++) {
                acc2[0][p] = fma2(d0, w[p], acc2[0][p]);
                acc2[1][p] = fma2(d1, w[p], acc2[1][p]);
                acc2[2][p] = fma2(d2, w[p], acc2[2][p]);
                acc2[3][p] = fma2(d3, w[p], acc2[3][p]);
            }
        }
    }
    __syncthreads();
    {
        float4 ba = *(const float4*)(b1 + fa);
        float4 bb4 = *(const float4*)(b1 + 128 + fa);
        float bias[8] = {ba.x, ba.y, ba.z, ba.w, bb4.x, bb4.y, bb4.z, bb4.w};
        float g[4][8];
        #pragma unroll
        for (int t = 0; t < 4; t++) {
            unpack2(acc2[t][0], g[t][0], g[t][1]);
            unpack2(acc2[t][1], g[t][2], g[t][3]);
            unpack2(acc2[t][2], g[t][4], g[t][5]);
            unpack2(acc2[t][3], g[t][6], g[t][7]);
            #pragma unroll
            for (int p = 0; p < 4; p++) acc2[t][p] = 0ULL;
        }
        #pragma unroll
        for (int j = 0; j < 8; j++) {
            int F = (j < 4) ? (fa + j) : (128 + fa + j - 4);
            *(float4*)(ht + F*36 + t0) = make_float4(
                gelu_exact(g[0][j] + bias[j]), gelu_exact(g[1][j] + bias[j]),
                gelu_exact(g[2][j] + bias[j]), gelu_exact(g[3][j] + bias[j]));
        }
    }

    for (int ks = 0; ks < 8; ks++) {
        __syncthreads();
        const float4* wsrc = (const float4*)(w2 + ks*32*256);
        float4* wdst = (float4*)ws;
        #pragma unroll
        for (int r = 0; r < 8; r++) wdst[tid + r*256] = wsrc[tid + r*256];
        __syncthreads();
        #pragma unroll 8
        for (int k = 0; k < 32; k++) {
            const float* wrow = ws + k*256 + fa;
            float4 av = *(const float4*)(ht + (ks*32 + k)*36 + t0);
            ulonglong2 wa = *(const ulonglong2*)(wrow);
            ulonglong2 wb = *(const ulonglong2*)(wrow + 128);
            u64 w[4] = {wa.x, wa.y, wb.x, wb.y};
            u64 d0 = dup2(av.x), d1 = dup2(av.y), d2 = dup2(av.z), d3 = dup2(av.w);
            #pragma unroll
            for (int p = 0; p < 4; p++) {
                acc2[0][p] = fma2(d0, w[p], acc2[0][p]);
                acc2[1][p] = fma2(d1, w[p], acc2[1][p]);
                acc2[2][p] = fma2(d2, w[p], acc2[2][p]);
                acc2[3][p] = fma2(d3, w[p], acc2[3][p]);
            }
        }
    }

    {
        float4 ba = *(const float4*)(b2 + fa);
        float4 bb4 = *(const float4*)(b2 + 128 + fa);
        float bias[8] = {ba.x, ba.y, ba.z, ba.w, bb4.x, bb4.y, bb4.z, bb4.w};
        float o[4][8];
        #pragma unroll
        for (int t = 0; t < 4; t++) {
            unpack2(acc2[t][0], o[t][0], o[t][1]);
            unpack2(acc2[t][1], o[t][2], o[t][3]);
            unpack2(acc2[t][2], o[t][4], o[t][5]);
            unpack2(acc2[t][3], o[t][6], o[t][7]);
            #pragma unroll
            for (int j = 0; j < 8; j++) o[t][j] += bias[j];
        }

        if (blockIdx.y == 2) {
            #pragma unroll
            for (int j = 0; j < 8; j++) {
                int F = (j < 4) ? (fa + j) : (128 + fa + j - 4);
                int h = F >> 6, d = F & 63;
                float* op = out + (((size_t)(b*HH + h))*LL + l0 + t0)*HD + d;
                #pragma unroll
                for (int t = 0; t < 4; t++) op[t*HD] = o[t][j];
            }
        } else {
            __syncthreads();
            #pragma unroll
            for (int j = 0; j < 8; j++) {
                int F = (j < 4) ? (fa + j) : (128 + fa + j - 4);
                *(float4*)(xt + F*36 + t0) = make_float4(o[0][j], o[1][j], o[2][j], o[3][j]);
            }
            __syncthreads();
            #pragma unroll
            for (int r = 0; r < 8; r++) {
                int idx = tid + r*256;
                int f = idx >> 3, i4 = idx & 7;
                *(float4*)(out + ((size_t)b*256 + f)*LL + l0 + i4*4) =
                    *(const float4*)(xt + f*36 + i4*4);
            }
        }
    }
}

// ---- Gram (R13 exact) ----------------------------------------------------------
__global__ void __launch_bounds__(256) gram_kernel() {
    extern __shared__ float Ks[];   // [64][260]
    const int bh = blockIdx.x, sl = blockIdx.y;
    const float* Kb = g_K + (size_t)bh*HD*LL;
    const int tid = threadIdx.x;
    const int d0 = (tid >> 4) << 2, e0 = (tid & 15) << 2;
    u64 acc2[4][4];
    #pragma unroll
    for (int i = 0; i < 4; i++)
        #pragma unroll
        for (int j = 0; j < 4; j++) acc2[i][j] = 0ULL;

    #pragma unroll
    for (int r = 0; r < 16; r++) {
        int idx = tid + r*256;
        int d = idx >> 6, c4 = idx & 63;
        *(float4*)(Ks + d*260 + c4*4) = *(const float4*)(Kb + (size_t)d*LL + sl*256 + c4*4);
    }
    __syncthreads();
    #pragma unroll 4
    for (int k2 = 0; k2 < 128; k2++) {
        u64 a[4], bv[4];
        #pragma unroll
        for (int i = 0; i < 4; i++) a[i]  = *(const u64*)(Ks + (d0+i)*260 + 2*k2);
        #pragma unroll
        for (int j = 0; j < 4; j++) bv[j] = *(const u64*)(Ks + (e0+j)*260 + 2*k2);
        #pragma unroll
        for (int i = 0; i < 4; i++)
            #pragma unroll
            for (int j = 0; j < 4; j++)
                acc2[i][j] = fma2(a[i], bv[j], acc2[i][j]);
    }
    float* Gp = g_G + (size_t)bh*HD*HD;
    #pragma unroll
    for (int i = 0; i < 4; i++)
        #pragma unroll
        for (int j = 0; j < 4; j++) {
            float lo, hi; unpack2(acc2[i][j], lo, hi);
            atomicAdd(Gp + (d0 + i)*HD + e0 + j, lo + hi);
        }
}

// ---- attention (R7 structure, deeper unroll) -----------------------------------
#define ATT_SMEM_BYTES ((64*132 + 64*68 + 64*68 + 64*132 + 2*128)*4)
__global__ void __launch_bounds__(256, 2) attn_kernel() {
    extern __shared__ float sm[];
    float* Qt   = sm;
    float* Kt   = Qt + 64*132;
    float* Vs   = Kt + 64*68;
    float* Pt   = Vs + 64*68;
    float* invd = Pt + 64*132;
    float* psum = invd + 128;

    const int tid = threadIdx.x;
    const int bh  = blockIdx.y;
    const int q0g = blockIdx.x << 7;

    const float* Qb = g_Q + (size_t)bh*HD*LL;
    #pragma unroll
    for (int r = 0; r < 8; r++) {
        int idx = tid + r*256;
        int d = idx >> 5, c4 = idx & 31;
        *(float4*)(Qt + d*132 + c4*4) = *(const float4*)(Qb + (size_t)d*LL + q0g + c4*4);
    }
    {
        const float* Gb = g_G + (size_t)bh*HD*HD;
        #pragma unroll
        for (int r = 0; r < 4; r++) {
            int idx = tid + r*256;
            int d = idx >> 4, c4 = idx & 15;
            *(float4*)(Pt + d*68 + c4*4) = *(const float4*)(Gb + d*64 + c4*4);
        }
    }
    __syncthreads();

    {
        int q = tid & 127, half = tid >> 7;
        float part = 0.f;
        for (int d = half*32; d < half*32 + 32; d++) {
            float qd = Qt[d*132 + q];
            float t = 0.f;
            #pragma unroll 16
            for (int e = 0; e < 64; e++)
                t = fmaf(Pt[d*68 + e], Qt[e*132 + q], t);
            part = fmaf(qd, t, part);
        }
        if (half == 0) { invd[q] = part; }
        __syncthreads();
        if (half == 1) {
            float ssq = invd[q] + part;
            __syncthreads();
            invd[q] = 1.0f / (sqrtf(fmaxf(ssq, 0.f)) + 8.0e-12f);
            psum[q] = 0.f;
        } else __syncthreads();
    }
    __syncthreads();

    const int kz = tid >> 7;
    const int ty = (tid >> 3) & 15, tx = tid & 7;
    const int qr = ty << 3;
    const int kc = kz*32 + tx*4;
    const int qg = ((tid >> 4) & 15) << 3;
    const int dg = (tid & 15) << 2;

    u64 s2[4][4];
    u64 Oacc[4][4];
    #pragma unroll
    for (int p = 0; p < 4; p++)
        #pragma unroll
        for (int c = 0; c < 4; c++) Oacc[p][c] = 0ULL;
    u64 rs2[4] = {0ULL,0ULL,0ULL,0ULL};
    u64 invd2[4];
    #pragma unroll
    for (int p = 0; p < 4; p++) invd2[p] = ((const u64*)(invd + qr))[p];

    const float* Kb = g_K + (size_t)bh*HD*LL;
    const float* Vb = g_V + (size_t)bh*LL*HD;

    for (int kt = 0; kt < 32; kt++) {
        __syncthreads();
        const int k0 = kt << 6;
        #pragma unroll
        for (int r = 0; r < 4; r++) {
            int idx = tid + r*256;
            int d = idx >> 4, c4 = idx & 15;
            *(float4*)(Kt + d*68 + c4*4) = *(const float4*)(Kb + (size_t)d*LL + k0 + c4*4);
        }
        #pragma unroll
        for (int r = 0; r < 4; r++) {
            int idx = tid + r*256;
            int row = idx >> 4, c4 = idx & 15;
            *(float4*)(Vs + row*68 + c4*4) = *(const float4*)(Vb + (size_t)(k0 + row)*HD + c4*4);
        }
        __syncthreads();

        #pragma unroll
        for (int p = 0; p < 4; p++)
            #pragma unroll
            for (int j = 0; j < 4; j++) s2[p][j] = 0ULL;
        #pragma unroll 8
        for (int d = 0; d < 64; d++) {
            ulonglong2 qa = *(const ulonglong2*)(Qt + d*132 + qr);
            ulonglong2 qb2v = *(const ulonglong2*)(Qt + d*132 + qr + 4);
            u64 qp[4] = {qa.x, qa.y, qb2v.x, qb2v.y};
            float4 kv = *(const float4*)(Kt + d*68 + kc);
            u64 kd[4] = {dup2(kv.x), dup2(kv.y), dup2(kv.z), dup2(kv.w)};
            #pragma unroll
            for (int p = 0; p < 4; p++)
                #pragma unroll
                for (int j = 0; j < 4; j++)
                    s2[p][j] = fma2(qp[p], kd[j], s2[p][j]);
        }

        #pragma unroll
        for (int p = 0; p < 4; p++) {
            #pragma unroll
            for (int j = 0; j < 4; j++) {
                u64 e = exp_poly2(mul2(s2[p][j], invd2[p]));
                s2[p][j] = e;
                rs2[p] = add2(rs2[p], e);
            }
        }
        #pragma unroll
        for (int j = 0; j < 4; j++) {
            ulonglong2 lo, hi;
            lo.x = s2[0][j]; lo.y = s2[1][j];
            hi.x = s2[2][j]; hi.y = s2[3][j];
            *(ulonglong2*)(Pt + (kc + j)*132 + qr)     = lo;
            *(ulonglong2*)(Pt + (kc + j)*132 + qr + 4) = hi;
        }
        __syncthreads();

        #pragma unroll 4
        for (int k = 0; k < 64; k++) {
            ulonglong2 pa = *(const ulonglong2*)(Pt + k*132 + qg);
            ulonglong2 pb = *(const ulonglong2*)(Pt + k*132 + qg + 4);
            u64 pp[4] = {pa.x, pa.y, pb.x, pb.y};
            float4 vf = *(const float4*)(Vs + k*68 + dg);
            u64 vd[4] = {dup2(vf.x), dup2(vf.y), dup2(vf.z), dup2(vf.w)};
            #pragma unroll
            for (int p = 0; p < 4; p++)
                #pragma unroll
                for (int c = 0; c < 4; c++)
                    Oacc[p][c] = fma2(pp[p], vd[c], Oacc[p][c]);
        }
    }

    #pragma unroll
    for (int p = 0; p < 4; p++) {
        float lo, hi; unpack2(rs2[p], lo, hi);
        atomicAdd(&psum[qr + 2*p],     lo);
        atomicAdd(&psum[qr + 2*p + 1], hi);
    }
    __syncthreads();

    const int b = bh >> 2, h = bh & 3;
    #pragma unroll
    for (int p = 0; p < 4; p++) {
        float ilo = 1.0f / psum[qg + 2*p];
        float ihi = 1.0f / psum[qg + 2*p + 1];
        float olo[4], ohi[4];
        #pragma unroll
        for (int c = 0; c < 4; c++) unpack2(Oacc[p][c], olo[c], ohi[c]);
        size_t row0 = (size_t)(b*LL + q0g + qg + 2*p)*CC + h*HD + dg;
        size_t row1 = row0 + CC;
        *(float4*)(g_AT + row0) = make_float4(olo[0]*ilo, olo[1]*ilo, olo[2]*ilo, olo[3]*ilo);
        *(float4*)(g_AT + row1) = make_float4(ohi[0]*ihi, ohi[1]*ihi, ohi[2]*ihi, ohi[3]*ihi);
    }
}

// ---- O-proj + LN + ELU + residual (R15 + 3 CTAs/SM) ----------------------------
__global__ void __launch_bounds__(256, 3) out_kernel(
    const float* __restrict__ x_in, const float* __restrict__ ow,
    const float* __restrict__ ob, const float* __restrict__ lng,
    const float* __restrict__ lnb, float* __restrict__ out)
{
    extern __shared__ float sm[];
    float* at = sm;               // [256][36]
    float* ws = sm + 256*36;      // [32][256]

    const int tok0 = blockIdx.x << 5;
    const int b = tok0 >> 11, l0 = tok0 & (LL-1);
    const int tid = threadIdx.x;

    #pragma unroll
    for (int r = 0; r < 32; r++) {
        int idx = tid + r*256;
        int t = idx >> 8, k = idx & 255;
        at[k*36 + t] = g_AT[(size_t)(tok0 + t)*CC + k];
    }

    const int tg = tid >> 5, fg = tid & 31;
    const int t0 = tg << 2;
    const int fa = fg << 2;

    u64 acc2[4][4];
    #pragma unroll
    for (int t = 0; t < 4; t++)
        #pragma unroll
        for (int p = 0; p < 4; p++) acc2[t][p] = 0ULL;

    for (int ks = 0; ks < 8; ks++) {
        __syncthreads();
        const float4* wsrc = (const float4*)(ow + ks*32*256);
        float4* wdst = (float4*)ws;
        #pragma unroll
        for (int r = 0; r < 8; r++) wdst[tid + r*256] = wsrc[tid + r*256];
        __syncthreads();
        #pragma unroll 8
        for (int k = 0; k < 32; k++) {
            const float* wrow = ws + k*256 + fa;
            float4 av = *(const float4*)(at + (ks*32 + k)*36 + t0);
            ulonglong2 wa = *(const ulonglong2*)(wrow);
            ulonglong2 wb = *(const ulonglong2*)(wrow + 128);
            u64 w[4] = {wa.x, wa.y, wb.x, wb.y};
            u64 d0 = dup2(av.x), d1 = dup2(av.y), d2 = dup2(av.z), d3 = dup2(av.w);
            #pragma unroll
            for (int p = 0; p < 4; p++) {
                acc2[0][p] = fma2(d0, w[p], acc2[0][p]);
                acc2[1][p] = fma2(d1, w[p], acc2[1][p]);
                acc2[2][p] = fma2(d2, w[p], acc2[2][p]);
                acc2[3][p] = fma2(d3, w[p], acc2[3][p]);
            }
        }
    }

    float o[4][8];
    float gv[8], bvv[8];
    {
        float4 ba = *(const float4*)(ob + fa);
        float4 bb4 = *(const float4*)(ob + 128 + fa);
        float bias[8] = {ba.x, ba.y, ba.z, ba.w, bb4.x, bb4.y, bb4.z, bb4.w};
        float4 ga = *(const float4*)(lng + fa);
        float4 gb4 = *(const float4*)(lng + 128 + fa);
        float4 be = *(const float4*)(lnb + fa);
        float4 be4 = *(const float4*)(lnb + 128 + fa);
        gv[0]=ga.x; gv[1]=ga.y; gv[2]=ga.z; gv[3]=ga.w;
        gv[4]=gb4.x; gv[5]=gb4.y; gv[6]=gb4.z; gv[7]=gb4.w;
        bvv[0]=be.x; bvv[1]=be.y; bvv[2]=be.z; bvv[3]=be.w;
        bvv[4]=be4.x; bvv[5]=be4.y; bvv[6]=be4.z; bvv[7]=be4.w;
        #pragma unroll
        for (int t = 0; t < 4; t++) {
            unpack2(acc2[t][0], o[t][0], o[t][1]);
            unpack2(acc2[t][1], o[t][2], o[t][3]);
            unpack2(acc2[t][2], o[t][4], o[t][5]);
            unpack2(acc2[t][3], o[t][6], o[t][7]);
            #pragma unroll
            for (int j = 0; j < 8; j++) o[t][j] += bias[j];
        }
    }
    __syncthreads();

    #pragma unroll
    for (int m = 0; m < 4; m++) {
        float s = 0.f, s2v = 0.f;
        #pragma unroll
        for (int j = 0; j < 8; j++) { s += o[m][j]; s2v = fmaf(o[m][j], o[m][j], s2v); }
        #pragma unroll
        for (int off = 16; off > 0; off >>= 1) {
            s   += __shfl_xor_sync(0xffffffffu, s,   off);
            s2v += __shfl_xor_sync(0xffffffffu, s2v, off);
        }
        float mu = s * (1.0f/256.0f);
        float var = fmaf(-mu, mu, s2v * (1.0f/256.0f));
        float rstd = rsqrtf(var + 1e-5f);
        #pragma unroll
        for (int j = 0; j < 8; j++) {
            int F = (j < 4) ? (fa + j) : (128 + fa + j - 4);
            at[F*36 + t0 + m] = fmaf((o[m][j] - mu) * rstd, gv[j], bvv[j]);
        }
    }
    __syncthreads();

    const float* xb = x_in + (size_t)b*CC*LL + l0;
    float* outb = out + (size_t)b*CC*LL + l0;
    #pragma unroll
    for (int r = 0; r < 32; r++) {
        int idx = tid + r*256;
        int t = idx & 31, f = idx >> 5;
        float y = at[f*36 + t];
        float e = (y > 0.f) ? y : expm1f(y);
        outb[(size_t)f*LL + t] = e + xb[(size_t)f*LL + t];
    }
}

extern "C" void kernel_launch(void* const* d_in, const int* in_sizes, int n_in,
                              void* d_out, int out_size) {
    const float* x    = (const float*)d_in[0];
    const float* qw1  = (const float*)d_in[1];
    const float* qb1  = (const float*)d_in[2];
    const float* qw2  = (const float*)d_in[3];
    const float* qb2  = (const float*)d_in[4];
    const float* kw1  = (const float*)d_in[5];
    const float* kb1  = (const float*)d_in[6];
    const float* kw2  = (const float*)d_in[7];
    const float* kb2  = (const float*)d_in[8];
    const float* vw1  = (const float*)d_in[9];
    const float* vb1  = (const float*)d_in[10];
    const float* vw2  = (const float*)d_in[11];
    const float* vb2  = (const float*)d_in[12];
    const float* ow   = (const float*)d_in[13];
    const float* ob   = (const float*)d_in[14];
    const float* lng  = (const float*)d_in[15];
    const float* lnb  = (const float*)d_in[16];
    float* out = (float*)d_out;

    const int mlp_smem  = (2*256*36 + 32*256)*4;
    const int out_smem  = (256*36 + 32*256)*4;
    const int gram_smem = 64*260*4;
    cudaFuncSetAttribute(mlp_kernel,  cudaFuncAttributeMaxDynamicSharedMemorySize, mlp_smem);
    cudaFuncSetAttribute(gram_kernel, cudaFuncAttributeMaxDynamicSharedMemorySize, gram_smem);
    cudaFuncSetAttribute(attn_kernel, cudaFuncAttributeMaxDynamicSharedMemorySize, ATT_SMEM_BYTES);
    cudaFuncSetAttribute(out_kernel,  cudaFuncAttributeMaxDynamicSharedMemorySize, out_smem);

    zero_G_kernel<<<128, 256>>>();
    mlp_kernel<<<dim3(512, 3), 256, mlp_smem>>>(x, qw1, qb1, qw2, qb2,
                                                kw1, kb1, kw2, kb2,
                                                vw1, vb1, vw2, vb2);
    gram_kernel<<<dim3(32, 8), 256, gram_smem>>>();
    attn_kernel<<<dim3(16, 32), 256, ATT_SMEM_BYTES>>>();
    out_kernel<<<512, 256, out_smem>>>(x, ow, ob, lng, lnb, out);
}

// round 17
// speedup vs baseline: 1.1020x; 1.0108x over previous
#include <cuda_runtime.h>
#include <math.h>

#define BB 8
#define CC 256
#define LL 2048
#define HH 4
#define HD 64
#define NTOK (BB*LL)
#define BHN (BB*HH)

typedef unsigned long long u64;
typedef unsigned int u32;

__device__ float g_Q[BHN*HD*LL];   // d-major [bh][d][l]
__device__ float g_K[BHN*HD*LL];   // d-major [bh][d][l]
__device__ float g_V[BHN*LL*HD];   // l-major [bh][l][d]
__device__ float g_G[BHN*HD*HD];
__device__ float g_AT[NTOK*CC];

__device__ __forceinline__ u64 dup2(float x){ u64 r; asm("mov.b64 %0,{%1,%1};":"=l"(r):"f"(x)); return r; }
__device__ __forceinline__ void unpack2(u64 v, float& lo, float& hi){ asm("mov.b64 {%0,%1},%2;":"=f"(lo),"=f"(hi):"l"(v)); }
__device__ __forceinline__ u64 fma2(u64 a,u64 b,u64 c){ u64 d; asm("fma.rn.f32x2 %0,%1,%2,%3;":"=l"(d):"l"(a),"l"(b),"l"(c)); return d; }
__device__ __forceinline__ u64 mul2(u64 a,u64 b){ u64 d; asm("mul.rn.f32x2 %0,%1,%2;":"=l"(d):"l"(a),"l"(b)); return d; }
__device__ __forceinline__ u64 add2(u64 a,u64 b){ u64 d; asm("add.rn.f32x2 %0,%1,%2;":"=l"(d):"l"(a),"l"(b)); return d; }

__device__ __forceinline__ void cp16(u32 s, const void* g){
    asm volatile("cp.async.ca.shared.global [%0], [%1], 16;" :: "r"(s), "l"(g) : "memory");
}
__device__ __forceinline__ void cp_commit(){ asm volatile("cp.async.commit_group;" ::: "memory"); }
__device__ __forceinline__ void cp_wait0(){ asm volatile("cp.async.wait_group 0;" ::: "memory"); }

__device__ __forceinline__ u64 exp_poly2(u64 t){
    u64 p = dup2(2.48015873e-5f);
    p = fma2(p, t, dup2(1.98412698e-4f));
    p = fma2(p, t, dup2(1.38888889e-3f));
    p = fma2(p, t, dup2(8.33333333e-3f));
    p = fma2(p, t, dup2(4.16666667e-2f));
    p = fma2(p, t, dup2(1.66666667e-1f));
    p = fma2(p, t, dup2(0.5f));
    p = fma2(p, t, dup2(1.0f));
    p = fma2(p, t, dup2(1.0f));
    return p;
}

__device__ __forceinline__ float gelu_exact(float x) {
    return 0.5f * x * (1.0f + erff(x * 0.70710678118654752f));
}

__global__ void zero_G_kernel() {
    int n = BHN*HD*HD;
    for (int i = blockIdx.x*blockDim.x + threadIdx.x; i < n; i += gridDim.x*blockDim.x)
        g_G[i] = 0.f;
}

// ---- fused MLP: cp.async double-buffered 16-row weight panels ---------------
__global__ void __launch_bounds__(256, 2) mlp_kernel(
    const float* __restrict__ x,
    const float* __restrict__ qw1, const float* __restrict__ qb1,
    const float* __restrict__ qw2, const float* __restrict__ qb2,
    const float* __restrict__ kw1, const float* __restrict__ kb1,
    const float* __restrict__ kw2, const float* __restrict__ kb2,
    const float* __restrict__ vw1, const float* __restrict__ vb1,
    const float* __restrict__ vw2, const float* __restrict__ vb2)
{
    extern __shared__ float sm[];
    float* xt  = sm;                // [256][36]
    float* ht  = sm + 256*36;       // [256][36]
    float* ws0 = sm + 2*256*36;     // [16][256]
    float* ws1 = ws0 + 16*256;      // [16][256]

    const float *w1, *b1, *w2, *b2; float* out;
    if (blockIdx.y == 0)      { w1=qw1; b1=qb1; w2=qw2; b2=qb2; out=g_Q; }
    else if (blockIdx.y == 1) { w1=kw1; b1=kb1; w2=kw2; b2=kb2; out=g_K; }
    else                      { w1=vw1; b1=vb1; w2=vw2; b2=vb2; out=g_V; }

    const int b  = blockIdx.x >> 6;
    const int l0 = (blockIdx.x & 63) << 5;
    const int tid = threadIdx.x;

    const float* xb = x + (size_t)b*CC*LL + l0;
    #pragma unroll
    for (int r = 0; r < 32; r++) {
        int idx = tid + r*256;
        xt[(idx >> 5)*36 + (idx & 31)] = xb[(size_t)(idx >> 5)*LL + (idx & 31)];
    }

    const int tg = tid >> 5, fg = tid & 31;
    const int t0 = tg << 2;
    const int fa = fg << 2;

    u32 w0a = (u32)__cvta_generic_to_shared(ws0);
    u32 w1a = (u32)__cvta_generic_to_shared(ws1);

    u64 acc2[4][4];
    #pragma unroll
    for (int t = 0; t < 4; t++)
        #pragma unroll
        for (int p = 0; p < 4; p++) acc2[t][p] = 0ULL;

    // ================= GEMM1: hidden = x @ w1 =================
    {
        const float4* src0 = (const float4*)w1;
        #pragma unroll
        for (int r = 0; r < 4; r++) {
            int idx = tid + r*256;
            cp16(w0a + idx*16, src0 + idx);
        }
        cp_commit(); cp_wait0(); __syncthreads();
    }
    for (int ks = 0; ks < 16; ks++) {
        const float* wc = (ks & 1) ? ws1 : ws0;
        if (ks + 1 < 16) {
            u32 dst = (ks & 1) ? w0a : w1a;
            const float4* src = (const float4*)(w1 + (ks + 1)*16*256);
            #pragma unroll
            for (int r = 0; r < 4; r++) {
                int idx = tid + r*256;
                cp16(dst + idx*16, src + idx);
            }
        }
        cp_commit();
        #pragma unroll 8
        for (int k = 0; k < 16; k++) {
            const float* wrow = wc + k*256 + fa;
            float4 av = *(const float4*)(xt + (ks*16 + k)*36 + t0);
            ulonglong2 wa = *(const ulonglong2*)(wrow);
            ulonglong2 wb = *(const ulonglong2*)(wrow + 128);
            u64 w[4] = {wa.x, wa.y, wb.x, wb.y};
            u64 d0 = dup2(av.x), d1 = dup2(av.y), d2 = dup2(av.z), d3 = dup2(av.w);
            #pragma unroll
            for (int p = 0; p < 4; p++) {
                acc2[0][p] = fma2(d0, w[p], acc2[0][p]);
                acc2[1][p] = fma2(d1, w[p], acc2[1][p]);
                acc2[2][p] = fma2(d2, w[p], acc2[2][p]);
                acc2[3][p] = fma2(d3, w[p], acc2[3][p]);
            }
        }
        cp_wait0();
        __syncthreads();
    }

    // gelu epilogue -> ht[f][t]
    {
        float4 ba = *(const float4*)(b1 + fa);
        float4 bb4 = *(const float4*)(b1 + 128 + fa);
        float bias[8] = {ba.x, ba.y, ba.z, ba.w, bb4.x, bb4.y, bb4.z, bb4.w};
        float g[4][8];
        #pragma unroll
        for (int t = 0; t < 4; t++) {
            unpack2(acc2[t][0], g[t][0], g[t][1]);
            unpack2(acc2[t][1], g[t][2], g[t][3]);
            unpack2(acc2[t][2], g[t][4], g[t][5]);
            unpack2(acc2[t][3], g[t][6], g[t][7]);
            #pragma unroll
            for (int p = 0; p < 4; p++) acc2[t][p] = 0ULL;
        }
        #pragma unroll
        for (int j = 0; j < 8; j++) {
            int F = (j < 4) ? (fa + j) : (128 + fa + j - 4);
            *(float4*)(ht + F*36 + t0) = make_float4(
                gelu_exact(g[0][j] + bias[j]), gelu_exact(g[1][j] + bias[j]),
                gelu_exact(g[2][j] + bias[j]), gelu_exact(g[3][j] + bias[j]));
        }
    }

    // ================= GEMM2: out = hidden @ w2 =================
    {
        const float4* src0 = (const float4*)w2;
        #pragma unroll
        for (int r = 0; r < 4; r++) {
            int idx = tid + r*256;
            cp16(w0a + idx*16, src0 + idx);
        }
        cp_commit(); cp_wait0(); __syncthreads();   // also orders ht writes
    }
    for (int ks = 0; ks < 16; ks++) {
        const float* wc = (ks & 1) ? ws1 : ws0;
        if (ks + 1 < 16) {
            u32 dst = (ks & 1) ? w0a : w1a;
            const float4* src = (const float4*)(w2 + (ks + 1)*16*256);
            #pragma unroll
            for (int r = 0; r < 4; r++) {
                int idx = tid + r*256;
                cp16(dst + idx*16, src + idx);
            }
        }
        cp_commit();
        #pragma unroll 8
        for (int k = 0; k < 16; k++) {
            const float* wrow = wc + k*256 + fa;
            float4 av = *(const float4*)(ht + (ks*16 + k)*36 + t0);
            ulonglong2 wa = *(const ulonglong2*)(wrow);
            ulonglong2 wb = *(const ulonglong2*)(wrow + 128);
            u64 w[4] = {wa.x, wa.y, wb.x, wb.y};
            u64 d0 = dup2(av.x), d1 = dup2(av.y), d2 = dup2(av.z), d3 = dup2(av.w);
            #pragma unroll
            for (int p = 0; p < 4; p++) {
                acc2[0][p] = fma2(d0, w[p], acc2[0][p]);
                acc2[1][p] = fma2(d1, w[p], acc2[1][p]);
                acc2[2][p] = fma2(d2, w[p], acc2[2][p]);
                acc2[3][p] = fma2(d3, w[p], acc2[3][p]);
            }
        }
        cp_wait0();
        __syncthreads();
    }

    {
        float4 ba = *(const float4*)(b2 + fa);
        float4 bb4 = *(const float4*)(b2 + 128 + fa);
        float bias[8] = {ba.x, ba.y, ba.z, ba.w, bb4.x, bb4.y, bb4.z, bb4.w};
        float o[4][8];
        #pragma unroll
        for (int t = 0; t < 4; t++) {
            unpack2(acc2[t][0], o[t][0], o[t][1]);
            unpack2(acc2[t][1], o[t][2], o[t][3]);
            unpack2(acc2[t][2], o[t][4], o[t][5]);
            unpack2(acc2[t][3], o[t][6], o[t][7]);
            #pragma unroll
            for (int j = 0; j < 8; j++) o[t][j] += bias[j];
        }

        if (blockIdx.y == 2) {
            #pragma unroll
            for (int j = 0; j < 8; j++) {
                int F = (j < 4) ? (fa + j) : (128 + fa + j - 4);
                int h = F >> 6, d = F & 63;
                float* op = out + (((size_t)(b*HH + h))*LL + l0 + t0)*HD + d;
                #pragma unroll
                for (int t = 0; t < 4; t++) op[t*HD] = o[t][j];
            }
        } else {
            __syncthreads();
            #pragma unroll
            for (int j = 0; j < 8; j++) {
                int F = (j < 4) ? (fa + j) : (128 + fa + j - 4);
                *(float4*)(xt + F*36 + t0) = make_float4(o[0][j], o[1][j], o[2][j], o[3][j]);
            }
            __syncthreads();
            #pragma unroll
            for (int r = 0; r < 8; r++) {
                int idx = tid + r*256;
                int f = idx >> 3, i4 = idx & 7;
                *(float4*)(out + ((size_t)b*256 + f)*LL + l0 + i4*4) =
                    *(const float4*)(xt + f*36 + i4*4);
            }
        }
    }
}

// ---- Gram (R13 exact) ----------------------------------------------------------
__global__ void __launch_bounds__(256) gram_kernel() {
    extern __shared__ float Ks[];   // [64][260]
    const int bh = blockIdx.x, sl = blockIdx.y;
    const float* Kb = g_K + (size_t)bh*HD*LL;
    const int tid = threadIdx.x;
    const int d0 = (tid >> 4) << 2, e0 = (tid & 15) << 2;
    u64 acc2[4][4];
    #pragma unroll
    for (int i = 0; i < 4; i++)
        #pragma unroll
        for (int j = 0; j < 4; j++) acc2[i][j] = 0ULL;

    #pragma unroll
    for (int r = 0; r < 16; r++) {
        int idx = tid + r*256;
        int d = idx >> 6, c4 = idx & 63;
        *(float4*)(Ks + d*260 + c4*4) = *(const float4*)(Kb + (size_t)d*LL + sl*256 + c4*4);
    }
    __syncthreads();
    #pragma unroll 4
    for (int k2 = 0; k2 < 128; k2++) {
        u64 a[4], bv[4];
        #pragma unroll
        for (int i = 0; i < 4; i++) a[i]  = *(const u64*)(Ks + (d0+i)*260 + 2*k2);
        #pragma unroll
        for (int j = 0; j < 4; j++) bv[j] = *(const u64*)(Ks + (e0+j)*260 + 2*k2);
        #pragma unroll
        for (int i = 0; i < 4; i++)
            #pragma unroll
            for (int j = 0; j < 4; j++)
                acc2[i][j] = fma2(a[i], bv[j], acc2[i][j]);
    }
    float* Gp = g_G + (size_t)bh*HD*HD;
    #pragma unroll
    for (int i = 0; i < 4; i++)
        #pragma unroll
        for (int j = 0; j < 4; j++) {
            float lo, hi; unpack2(acc2[i][j], lo, hi);
            atomicAdd(Gp + (d0 + i)*HD + e0 + j, lo + hi);
        }
}

// ---- attention (R16 exact) -------------------------------------------------------
#define ATT_SMEM_BYTES ((64*132 + 64*68 + 64*68 + 64*132 + 2*128)*4)
__global__ void __launch_bounds__(256, 2) attn_kernel() {
    extern __shared__ float sm[];
    float* Qt   = sm;
    float* Kt   = Qt + 64*132;
    float* Vs   = Kt + 64*68;
    float* Pt   = Vs + 64*68;
    float* invd = Pt + 64*132;
    float* psum = invd + 128;

    const int tid = threadIdx.x;
    const int bh  = blockIdx.y;
    const int q0g = blockIdx.x << 7;

    const float* Qb = g_Q + (size_t)bh*HD*LL;
    #pragma unroll
    for (int r = 0; r < 8; r++) {
        int idx = tid + r*256;
        int d = idx >> 5, c4 = idx & 31;
        *(float4*)(Qt + d*132 + c4*4) = *(const float4*)(Qb + (size_t)d*LL + q0g + c4*4);
    }
    {
        const float* Gb = g_G + (size_t)bh*HD*HD;
        #pragma unroll
        for (int r = 0; r < 4; r++) {
            int idx = tid + r*256;
            int d = idx >> 4, c4 = idx & 15;
            *(float4*)(Pt + d*68 + c4*4) = *(const float4*)(Gb + d*64 + c4*4);
        }
    }
    __syncthreads();

    {
        int q = tid & 127, half = tid >> 7;
        float part = 0.f;
        for (int d = half*32; d < half*32 + 32; d++) {
            float qd = Qt[d*132 + q];
            float t = 0.f;
            #pragma unroll 16
            for (int e = 0; e < 64; e++)
                t = fmaf(Pt[d*68 + e], Qt[e*132 + q], t);
            part = fmaf(qd, t, part);
        }
        if (half == 0) { invd[q] = part; }
        __syncthreads();
        if (half == 1) {
            float ssq = invd[q] + part;
            __syncthreads();
            invd[q] = 1.0f / (sqrtf(fmaxf(ssq, 0.f)) + 8.0e-12f);
            psum[q] = 0.f;
        } else __syncthreads();
    }
    __syncthreads();

    const int kz = tid >> 7;
    const int ty = (tid >> 3) & 15, tx = tid & 7;
    const int qr = ty << 3;
    const int kc = kz*32 + tx*4;
    const int qg = ((tid >> 4) & 15) << 3;
    const int dg = (tid & 15) << 2;

    u64 s2[4][4];
    u64 Oacc[4][4];
    #pragma unroll
    for (int p = 0; p < 4; p++)
        #pragma unroll
        for (int c = 0; c < 4; c++) Oacc[p][c] = 0ULL;
    u64 rs2[4] = {0ULL,0ULL,0ULL,0ULL};
    u64 invd2[4];
    #pragma unroll
    for (int p = 0; p < 4; p++) invd2[p] = ((const u64*)(invd + qr))[p];

    const float* Kb = g_K + (size_t)bh*HD*LL;
    const float* Vb = g_V + (size_t)bh*LL*HD;

    for (int kt = 0; kt < 32; kt++) {
        __syncthreads();
        const int k0 = kt << 6;
        #pragma unroll
        for (int r = 0; r < 4; r++) {
            int idx = tid + r*256;
            int d = idx >> 4, c4 = idx & 15;
            *(float4*)(Kt + d*68 + c4*4) = *(const float4*)(Kb + (size_t)d*LL + k0 + c4*4);
        }
        #pragma unroll
        for (int r = 0; r < 4; r++) {
            int idx = tid + r*256;
            int row = idx >> 4, c4 = idx & 15;
            *(float4*)(Vs + row*68 + c4*4) = *(const float4*)(Vb + (size_t)(k0 + row)*HD + c4*4);
        }
        __syncthreads();

        #pragma unroll
        for (int p = 0; p < 4; p++)
            #pragma unroll
            for (int j = 0; j < 4; j++) s2[p][j] = 0ULL;
        #pragma unroll 8
        for (int d = 0; d < 64; d++) {
            ulonglong2 qa = *(const ulonglong2*)(Qt + d*132 + qr);
            ulonglong2 qb2v = *(const ulonglong2*)(Qt + d*132 + qr + 4);
            u64 qp[4] = {qa.x, qa.y, qb2v.x, qb2v.y};
            float4 kv = *(const float4*)(Kt + d*68 + kc);
            u64 kd[4] = {dup2(kv.x), dup2(kv.y), dup2(kv.z), dup2(kv.w)};
            #pragma unroll
            for (int p = 0; p < 4; p++)
                #pragma unroll
                for (int j = 0; j < 4; j++)
                    s2[p][j] = fma2(qp[p], kd[j], s2[p][j]);
        }

        #pragma unroll
        for (int p = 0; p < 4; p++) {
            #pragma unroll
            for (int j = 0; j < 4; j++) {
                u64 e = exp_poly2(mul2(s2[p][j], invd2[p]));
                s2[p][j] = e;
                rs2[p] = add2(rs2[p], e);
            }
        }
        #pragma unroll
        for (int j = 0; j < 4; j++) {
            ulonglong2 lo, hi;
            lo.x = s2[0][j]; lo.y = s2[1][j];
            hi.x = s2[2][j]; hi.y = s2[3][j];
            *(ulonglong2*)(Pt + (kc + j)*132 + qr)     = lo;
            *(ulonglong2*)(Pt + (kc + j)*132 + qr + 4) = hi;
        }
        __syncthreads();

        #pragma unroll 4
        for (int k = 0; k < 64; k++) {
            ulonglong2 pa = *(const ulonglong2*)(Pt + k*132 + qg);
            ulonglong2 pb = *(const ulonglong2*)(Pt + k*132 + qg + 4);
            u64 pp[4] = {pa.x, pa.y, pb.x, pb.y};
            float4 vf = *(const float4*)(Vs + k*68 + dg);
            u64 vd[4] = {dup2(vf.x), dup2(vf.y), dup2(vf.z), dup2(vf.w)};
            #pragma unroll
            for (int p = 0; p < 4; p++)
                #pragma unroll
                for (int c = 0; c < 4; c++)
                    Oacc[p][c] = fma2(pp[p], vd[c], Oacc[p][c]);
        }
    }

    #pragma unroll
    for (int p = 0; p < 4; p++) {
        float lo, hi; unpack2(rs2[p], lo, hi);
        atomicAdd(&psum[qr + 2*p],     lo);
        atomicAdd(&psum[qr + 2*p + 1], hi);
    }
    __syncthreads();

    const int b = bh >> 2, h = bh & 3;
    #pragma unroll
    for (int p = 0; p < 4; p++) {
        float ilo = 1.0f / psum[qg + 2*p];
        float ihi = 1.0f / psum[qg + 2*p + 1];
        float olo[4], ohi[4];
        #pragma unroll
        for (int c = 0; c < 4; c++) unpack2(Oacc[p][c], olo[c], ohi[c]);
        size_t row0 = (size_t)(b*LL + q0g + qg + 2*p)*CC + h*HD + dg;
        size_t row1 = row0 + CC;
        *(float4*)(g_AT + row0) = make_float4(olo[0]*ilo, olo[1]*ilo, olo[2]*ilo, olo[3]*ilo);
        *(float4*)(g_AT + row1) = make_float4(ohi[0]*ihi, ohi[1]*ihi, ohi[2]*ihi, ohi[3]*ihi);
    }
}

// ---- O-proj + LN + ELU + residual (R16 exact) -----------------------------------
__global__ void __launch_bounds__(256, 3) out_kernel(
    const float* __restrict__ x_in, const float* __restrict__ ow,
    const float* __restrict__ ob, const float* __restrict__ lng,
    const float* __restrict__ lnb, float* __restrict__ out)
{
    extern __shared__ float sm[];
    float* at = sm;               // [256][36]
    float* ws = sm + 256*36;      // [32][256]

    const int tok0 = blockIdx.x << 5;
    const int b = tok0 >> 11, l0 = tok0 & (LL-1);
    const int tid = threadIdx.x;

    #pragma unroll
    for (int r = 0; r < 32; r++) {
        int idx = tid + r*256;
        int t = idx >> 8, k = idx & 255;
        at[k*36 + t] = g_AT[(size_t)(tok0 + t)*CC + k];
    }

    const int tg = tid >> 5, fg = tid & 31;
    const int t0 = tg << 2;
    const int fa = fg << 2;

    u64 acc2[4][4];
    #pragma unroll
    for (int t = 0; t < 4; t++)
        #pragma unroll
        for (int p = 0; p < 4; p++) acc2[t][p] = 0ULL;

    for (int ks = 0; ks < 8; ks++) {
        __syncthreads();
        const float4* wsrc = (const float4*)(ow + ks*32*256);
        float4* wdst = (float4*)ws;
        #pragma unroll
        for (int r = 0; r < 8; r++) wdst[tid + r*256] = wsrc[tid + r*256];
        __syncthreads();
        #pragma unroll 8
        for (int k = 0; k < 32; k++) {
            const float* wrow = ws + k*256 + fa;
            float4 av = *(const float4*)(at + (ks*32 + k)*36 + t0);
            ulonglong2 wa = *(const ulonglong2*)(wrow);
            ulonglong2 wb = *(const ulonglong2*)(wrow + 128);
            u64 w[4] = {wa.x, wa.y, wb.x, wb.y};
            u64 d0 = dup2(av.x), d1 = dup2(av.y), d2 = dup2(av.z), d3 = dup2(av.w);
            #pragma unroll
            for (int p = 0; p < 4; p++) {
                acc2[0][p] = fma2(d0, w[p], acc2[0][p]);
                acc2[1][p] = fma2(d1, w[p], acc2[1][p]);
                acc2[2][p] = fma2(d2, w[p], acc2[2][p]);
                acc2[3][p] = fma2(d3, w[p], acc2[3][p]);
            }
        }
    }

    float o[4][8];
    float gv[8], bvv[8];
    {
        float4 ba = *(const float4*)(ob + fa);
        float4 bb4 = *(const float4*)(ob + 128 + fa);
        float bias[8] = {ba.x, ba.y, ba.z, ba.w, bb4.x, bb4.y, bb4.z, bb4.w};
        float4 ga = *(const float4*)(lng + fa);
        float4 gb4 = *(const float4*)(lng + 128 + fa);
        float4 be = *(const float4*)(lnb + fa);
        float4 be4 = *(const float4*)(lnb + 128 + fa);
        gv[0]=ga.x; gv[1]=ga.y; gv[2]=ga.z; gv[3]=ga.w;
        gv[4]=gb4.x; gv[5]=gb4.y; gv[6]=gb4.z; gv[7]=gb4.w;
        bvv[0]=be.x; bvv[1]=be.y; bvv[2]=be.z; bvv[3]=be.w;
        bvv[4]=be4.x; bvv[5]=be4.y; bvv[6]=be4.z; bvv[7]=be4.w;
        #pragma unroll
        for (int t = 0; t < 4; t++) {
            unpack2(acc2[t][0], o[t][0], o[t][1]);
            unpack2(acc2[t][1], o[t][2], o[t][3]);
            unpack2(acc2[t][2], o[t][4], o[t][5]);
            unpack2(acc2[t][3], o[t][6], o[t][7]);
            #pragma unroll
            for (int j = 0; j < 8; j++) o[t][j] += bias[j];
        }
    }
    __syncthreads();

    #pragma unroll
    for (int m = 0; m < 4; m++) {
        float s = 0.f, s2v = 0.f;
        #pragma unroll
        for (int j = 0; j < 8; j++) { s += o[m][j]; s2v = fmaf(o[m][j], o[m][j], s2v); }
        #pragma unroll
        for (int off = 16; off > 0; off >>= 1) {
            s   += __shfl_xor_sync(0xffffffffu, s,   off);
            s2v += __shfl_xor_sync(0xffffffffu, s2v, off);
        }
        float mu = s * (1.0f/256.0f);
        float var = fmaf(-mu, mu, s2v * (1.0f/256.0f));
        float rstd = rsqrtf(var + 1e-5f);
        #pragma unroll
        for (int j = 0; j < 8; j++) {
            int F = (j < 4) ? (fa + j) : (128 + fa + j - 4);
            at[F*36 + t0 + m] = fmaf((o[m][j] - mu) * rstd, gv[j], bvv[j]);
        }
    }
    __syncthreads();

    const float* xb = x_in + (size_t)b*CC*LL + l0;
    float* outb = out + (size_t)b*CC*LL + l0;
    #pragma unroll
    for (int r = 0; r < 32; r++) {
        int idx = tid + r*256;
        int t = idx & 31, f = idx >> 5;
        float y = at[f*36 + t];
        float e = (y > 0.f) ? y : expm1f(y);
        outb[(size_t)f*LL + t] = e + xb[(size_t)f*LL + t];
    }
}

extern "C" void kernel_launch(void* const* d_in, const int* in_sizes, int n_in,
                              void* d_out, int out_size) {
    const float* x    = (const float*)d_in[0];
    const float* qw1  = (const float*)d_in[1];
    const float* qb1  = (const float*)d_in[2];
    const float* qw2  = (const float*)d_in[3];
    const float* qb2  = (const float*)d_in[4];
    const float* kw1  = (const float*)d_in[5];
    const float* kb1  = (const float*)d_in[6];
    const float* kw2  = (const float*)d_in[7];
    const float* kb2  = (const float*)d_in[8];
    const float* vw1  = (const float*)d_in[9];
    const float* vb1  = (const float*)d_in[10];
    const float* vw2  = (const float*)d_in[11];
    const float* vb2  = (const float*)d_in[12];
    const float* ow   = (const float*)d_in[13];
    const float* ob   = (const float*)d_in[14];
    const float* lng  = (const float*)d_in[15];
    const float* lnb  = (const float*)d_in[16];
    float* out = (float*)d_out;

    const int mlp_smem  = (2*256*36 + 2*16*256)*4;
    const int out_smem  = (256*36 + 32*256)*4;
    const int gram_smem = 64*260*4;
    cudaFuncSetAttribute(mlp_kernel,  cudaFuncAttributeMaxDynamicSharedMemorySize, mlp_smem);
    cudaFuncSetAttribute(gram_kernel, cudaFuncAttributeMaxDynamicSharedMemorySize, gram_smem);
    cudaFuncSetAttribute(attn_kernel, cudaFuncAttributeMaxDynamicSharedMemorySize, ATT_SMEM_BYTES);
    cudaFuncSetAttribute(out_kernel,  cudaFuncAttributeMaxDynamicSharedMemorySize, out_smem);

    zero_G_kernel<<<128, 256>>>();
    mlp_kernel<<<dim3(512, 3), 256, mlp_smem>>>(x, qw1, qb1, qw2, qb2,
                                                kw1, kb1, kw2, kb2,
                                                vw1, vb1, vw2, vb2);
    gram_kernel<<<dim3(32, 8), 256, gram_smem>>>();
    attn_kernel<<<dim3(16, 32), 256, ATT_SMEM_BYTES>>>();
    out_kernel<<<512, 256, out_smem>>>(x, ow, ob, lng, lnb, out);
}